// round 13
// baseline (speedup 1.0000x reference)
#include <cuda_runtime.h>
#include <math.h>

#define R_TOT 2048   // B*C rows
#define N0 8192
#define M1 4099
#define M2 2053
#define M3 1030
#define M4 518
#define M1P 4100
#define M2P 2056
#define M3P 1032
#define M4P 520
#define CB 64
#define BB 32

__constant__ float c_dlo[8] = {-0.010597401784997278f, 0.032883011666982945f, 0.030841381835986965f,
                               -0.18703481171888114f, -0.02798376941698385f, 0.6308807679295904f,
                               0.7148465705525415f, 0.23037781330885523f};
__constant__ float c_dhi[8] = {-0.23037781330885523f, 0.7148465705525415f, -0.6308807679295904f,
                               -0.02798376941698385f, 0.18703481171888114f, 0.030841381835986965f,
                               -0.032883011666982945f, -0.010597401784997278f};
// packed (dlo[j], dhi[j]) pairs for f32x2 math
__constant__ float2 c_lh[8] = {
    {-0.010597401784997278f, -0.23037781330885523f},
    {0.032883011666982945f,  0.7148465705525415f},
    {0.030841381835986965f,  -0.6308807679295904f},
    {-0.18703481171888114f,  -0.02798376941698385f},
    {-0.02798376941698385f,  0.18703481171888114f},
    {0.6308807679295904f,    0.030841381835986965f},
    {0.7148465705525415f,    -0.032883011666982945f},
    {0.23037781330885523f,   -0.010597401784997278f}};

typedef unsigned long long u64;
__device__ __forceinline__ u64 ffma2(u64 a, u64 b, u64 c) {
    u64 d;
    asm("fma.rn.f32x2 %0, %1, %2, %3;" : "=l"(d) : "l"(a), "l"(b), "l"(c));
    return d;
}
__device__ __forceinline__ u64 pk2(float x, float y) {
    u64 r;
    asm("mov.b64 %0, {%1, %2};" : "=l"(r) : "f"(x), "f"(y));
    return r;
}
__device__ __forceinline__ float2 up2(u64 v) {
    float2 r;
    asm("mov.b64 {%0, %1}, %2;" : "=f"(r.x), "=f"(r.y) : "l"(v));
    return r;
}

// Scratch (static device globals; allocation-free per harness rules)
__device__ __align__(256) float g_d1[(size_t)R_TOT * M1P];
__device__ __align__(256) float g_a2[(size_t)R_TOT * M2P];   // fwd a2, later a2-recon
__device__ __align__(256) float g_d2[(size_t)R_TOT * M2P];
__device__ __align__(256) float g_d3[(size_t)R_TOT * M3P];
__device__ __align__(256) float g_a4[(size_t)R_TOT * M4P];
__device__ __align__(256) float g_d4[(size_t)R_TOT * M4P];
__device__ __align__(256) float g_a4t[(size_t)M4 * R_TOT];   // [k][row]
__device__ __align__(256) float g_d4t[(size_t)M4 * R_TOT];
__device__ __align__(256) float g_a4mt[(size_t)M4 * R_TOT];
__device__ __align__(256) float g_d4mt[(size_t)M4 * R_TOT];
__device__ __align__(256) float g_a4m[(size_t)R_TOT * M4P];  // [row][k]
__device__ __align__(256) float g_d4m[(size_t)R_TOT * M4P];
__device__ __align__(256) float g_wt1[(size_t)M4 * CB * CB]; // [k][i*64+o]
__device__ __align__(256) float g_wt2[(size_t)M4 * CB * CB];

// ---------------------------------------------------------------------------
// K1: fused transpose + DWT L1 + L2 (halo recompute). a1 only in SMEM.
// ---------------------------------------------------------------------------
__device__ __forceinline__ void dwt12_a1_body(
    int cc, int kk, int K0, int b, int c0,
    const float* __restrict__ xe, const float* __restrict__ xo,
    float* __restrict__ ae, float* __restrict__ ao,
    float* __restrict__ d1, const u64* __restrict__ lh) {
    int k1 = 2 * K0 - 6 + kk;
    if (k1 < 0 || k1 >= M1) return;
    const float* pe = &xe[cc * 139 + kk + 3];
    const float* po = &xo[cc * 139 + kk + 3];
    u64 acc = 0ull;
#pragma unroll
    for (int s = 0; s < 4; s++) {
        float vo = po[-s], ve = pe[-s];
        acc = ffma2(pk2(vo, vo), lh[2 * s], acc);
        acc = ffma2(pk2(ve, ve), lh[2 * s + 1], acc);
    }
    float2 ad = up2(acc);
    int tl = (k1 >> 1) - (K0 - 3);
    if (k1 & 1) ao[cc * 68 + tl] = ad.x;
    else        ae[cc * 68 + tl] = ad.x;
    if (kk >= 6) d1[(size_t)(b * 64 + c0 + cc) * M1P + k1] = ad.y;
}

__global__ __launch_bounds__(256) void dwt12_kernel(const float* __restrict__ x,
                                                    float* __restrict__ d1,
                                                    float* __restrict__ a2,
                                                    float* __restrict__ d2) {
    extern __shared__ float sm[];
    float* xe = sm;                 // [32][139]
    float* xo = sm + 32 * 139;      // [32][139]
    float* ae = sm + 2 * 32 * 139;  // [32][68]
    float* ao = ae + 32 * 68;       // [32][68]
    int K0 = blockIdx.x * 64;
    int ct = blockIdx.y;
    int b = ct >> 1, c0 = (ct & 1) * 32;
    int tid = threadIdx.x;
    int xbase = 4 * K0 - 18;        // even
    const u64* lh = reinterpret_cast<const u64*>(c_lh);

    // x window via float4 over channels: 276 rows x 8 cgroups
    for (int idx = tid; idx < 276 * 8; idx += 256) {
        int nn = idx >> 3, cg = idx & 7;
        int q = xbase + nn;
        q = (q < 0) ? (-1 - q) : q;
        q = (q >= N0) ? (2 * N0 - 1 - q) : q;
        float4 v = __ldg(reinterpret_cast<const float4*>(&x[((size_t)b * N0 + q) * CB + c0 + cg * 4]));
        int u = nn >> 1;
        float* dst = (nn & 1) ? xo : xe;
        int cb4 = cg * 4;
        dst[(cb4 + 0) * 139 + u] = v.x;
        dst[(cb4 + 1) * 139 + u] = v.y;
        dst[(cb4 + 2) * 139 + u] = v.z;
        dst[(cb4 + 3) * 139 + u] = v.w;
    }
    __syncthreads();

    // a1 window [2K0-6, 2K0+127] (kk 0..133): pow2 main loop + tail (no division)
    for (int idx = tid; idx < 32 * 128; idx += 256) {
        dwt12_a1_body(idx >> 7, idx & 127, K0, b, c0, xe, xo, ae, ao, d1, lh);
    }
    {   // tail kk 128..133
        int cc = tid >> 3, kk = 128 + (tid & 7);
        if (kk < 134) dwt12_a1_body(cc, kk, K0, b, c0, xe, xo, ae, ao, d1, lh);
    }
    __syncthreads();

    // level 2
    for (int idx = tid; idx < 32 * 64; idx += 256) {
        int cc = idx >> 6, kk2 = idx & 63;
        int k2 = K0 + kk2;
        if (k2 >= M2) continue;
        float sa, sd;
        if (k2 >= 3 && k2 <= 2048) {
            const float* pe = &ae[cc * 68 + kk2 + 3];
            const float* po = &ao[cc * 68 + kk2 + 3];
            u64 acc = 0ull;
#pragma unroll
            for (int s = 0; s < 4; s++) {
                float vo = po[-s], ve = pe[-s];
                acc = ffma2(pk2(vo, vo), lh[2 * s], acc);
                acc = ffma2(pk2(ve, ve), lh[2 * s + 1], acc);
            }
            float2 ad = up2(acc);
            sa = ad.x; sd = ad.y;
        } else {
            sa = 0.f; sd = 0.f;
#pragma unroll
            for (int j = 0; j < 8; j++) {
                int g = 2 * k2 + 1 - j;
                g = (g < 0) ? (-1 - g) : g;
                g = (g >= M1) ? (2 * M1 - 1 - g) : g;
                int tl = (g >> 1) - (K0 - 3);
                float v = (g & 1) ? ao[cc * 68 + tl] : ae[cc * 68 + tl];
                sa = fmaf(v, c_dlo[j], sa);
                sd = fmaf(v, c_dhi[j], sd);
            }
        }
        size_t off = (size_t)(b * 64 + c0 + cc) * M2P + k2;
        a2[off] = sa;
        d2[off] = sd;
    }
}

// ---------------------------------------------------------------------------
// K2: fused DWT L3 + L4 per row. a3 only in SMEM.
// ---------------------------------------------------------------------------
__global__ __launch_bounds__(256) void dwt34_kernel(const float* __restrict__ a2,
                                                    float* __restrict__ d3,
                                                    float* __restrict__ a4,
                                                    float* __restrict__ d4) {
    __shared__ __align__(16) float s2e[1032];
    __shared__ __align__(16) float s2o[1032];
    __shared__ __align__(16) float a3e[520];
    __shared__ __align__(16) float a3o[520];
    int row = blockIdx.x, tid = threadIdx.x;
    const u64* lh = reinterpret_cast<const u64*>(c_lh);
    const float4* s4 = reinterpret_cast<const float4*>(a2 + (size_t)row * M2P);
    for (int i = tid; i < 514; i += 256) {
        float4 v = __ldg(&s4[i]);
        int u = 2 * i;
        s2e[u] = v.x; s2o[u] = v.y; s2e[u + 1] = v.z; s2o[u + 1] = v.w;
    }
    __syncthreads();
    float* d3r = d3 + (size_t)row * M3P;
    for (int k = tid; k < M3; k += 256) {
        float sa, sd;
        if (k >= 3 && k <= 1025) {
            u64 acc = 0ull;
#pragma unroll
            for (int s = 0; s < 4; s++) {
                float vo = s2o[k - s], ve = s2e[k - s];
                acc = ffma2(pk2(vo, vo), lh[2 * s], acc);
                acc = ffma2(pk2(ve, ve), lh[2 * s + 1], acc);
            }
            float2 ad = up2(acc);
            sa = ad.x; sd = ad.y;
        } else {
            sa = 0.f; sd = 0.f;
#pragma unroll
            for (int j = 0; j < 8; j++) {
                int g = 2 * k + 1 - j;
                g = (g < 0) ? (-1 - g) : g;
                g = (g >= M2) ? (2 * M2 - 1 - g) : g;
                float v = (g & 1) ? s2o[g >> 1] : s2e[g >> 1];
                sa = fmaf(v, c_dlo[j], sa);
                sd = fmaf(v, c_dhi[j], sd);
            }
        }
        if (k & 1) a3o[k >> 1] = sa; else a3e[k >> 1] = sa;
        d3r[k] = sd;
    }
    __syncthreads();
    float* a4r = a4 + (size_t)row * M4P;
    float* d4r = d4 + (size_t)row * M4P;
    for (int k = tid; k < M4; k += 256) {
        float sa, sd;
        if (k >= 3 && k <= 514) {
            u64 acc = 0ull;
#pragma unroll
            for (int s = 0; s < 4; s++) {
                float vo = a3o[k - s], ve = a3e[k - s];
                acc = ffma2(pk2(vo, vo), lh[2 * s], acc);
                acc = ffma2(pk2(ve, ve), lh[2 * s + 1], acc);
            }
            float2 ad = up2(acc);
            sa = ad.x; sd = ad.y;
        } else {
            sa = 0.f; sd = 0.f;
#pragma unroll
            for (int j = 0; j < 8; j++) {
                int g = 2 * k + 1 - j;
                g = (g < 0) ? (-1 - g) : g;
                g = (g >= M3) ? (2 * M3 - 1 - g) : g;
                float v = (g & 1) ? a3o[g >> 1] : a3e[g >> 1];
                sa = fmaf(v, c_dlo[j], sa);
                sd = fmaf(v, c_dhi[j], sd);
            }
        }
        a4r[k] = sa;
        d4r[k] = sd;
    }
}

// ---------------------------------------------------------------------------
// Forward transposes (z=0: a4->a4t, 1: d4->d4t, 2: w1->wt1, 3: w2->wt2)
// ---------------------------------------------------------------------------
__global__ void tr4_kernel(const float* __restrict__ s0, const float* __restrict__ s1,
                           const float* __restrict__ s2, const float* __restrict__ s3,
                           float* __restrict__ o0, float* __restrict__ o1,
                           float* __restrict__ o2, float* __restrict__ o3) {
    __shared__ float tile[32][33];
    int z = blockIdx.z;
    const float* __restrict__ src; float* __restrict__ dst; int R, ss, ds;
    if (z == 0)      { src = s0; dst = o0; R = R_TOT; ss = M4P; ds = R_TOT; }
    else if (z == 1) { src = s1; dst = o1; R = R_TOT; ss = M4P; ds = R_TOT; }
    else if (z == 2) { src = s2; dst = o2; R = 4096;  ss = M4;  ds = 4096; }
    else             { src = s3; dst = o3; R = 4096;  ss = M4;  ds = 4096; }
    int c0 = blockIdx.x * 32;
    int r0 = blockIdx.y * 32;
    if (r0 >= R) return;
    int tx = threadIdx.x, ty = threadIdx.y;
#pragma unroll
    for (int i = 0; i < 32; i += 8) {
        int r = r0 + ty + i, c = c0 + tx;
        if (r < R && c < M4) tile[ty + i][tx] = src[(size_t)r * ss + c];
    }
    __syncthreads();
#pragma unroll
    for (int i = 0; i < 32; i += 8) {
        int c = c0 + ty + i, r = r0 + tx;
        if (c < M4 && r < R) dst[(size_t)c * ds + r] = tile[tx][ty + i];
    }
}

// ---------------------------------------------------------------------------
// Back transposes (z=0: a4mt->a4m, 1: d4mt->d4m)
// ---------------------------------------------------------------------------
__global__ void tr2_kernel(const float* __restrict__ s0, const float* __restrict__ s1,
                           float* __restrict__ o0, float* __restrict__ o1) {
    __shared__ float tile[32][33];
    const float* __restrict__ src = blockIdx.z ? s1 : s0;
    float* __restrict__ dst = blockIdx.z ? o1 : o0;
    int c0 = blockIdx.x * 32;
    int r0 = blockIdx.y * 32;
    int tx = threadIdx.x, ty = threadIdx.y;
#pragma unroll
    for (int i = 0; i < 32; i += 8) {
        int r = r0 + ty + i;
        if (r < M4) tile[ty + i][tx] = src[(size_t)r * R_TOT + c0 + tx];
    }
    __syncthreads();
#pragma unroll
    for (int i = 0; i < 32; i += 8) {
        int r = r0 + tx;
        if (r < M4) dst[(size_t)(c0 + ty + i) * M4P + r] = tile[tx][ty + i];
    }
}

// ---------------------------------------------------------------------------
// Channel mix: 2 batches per thread share each w load; f32x2 accumulate. (R12 WIN)
// ---------------------------------------------------------------------------
__global__ __launch_bounds__(256) void mix_kernel(
    const float* __restrict__ a4t, const float* __restrict__ d4t,
    const float* __restrict__ wt1, const float* __restrict__ wt2,
    float* __restrict__ a4mt, float* __restrict__ d4mt) {
    int k = blockIdx.x;
    const float* __restrict__ in = blockIdx.y ? d4t : a4t;
    const float* __restrict__ wt = blockIdx.y ? wt2 : wt1;
    float* __restrict__ out = blockIdx.y ? d4mt : a4mt;

    __shared__ __align__(16) float ws[4096];
    __shared__ float as[32 * 65];
    int tid = threadIdx.x;
    const float4* __restrict__ wk4 = reinterpret_cast<const float4*>(wt + (size_t)k * 4096);
    const float4* __restrict__ ik4 = reinterpret_cast<const float4*>(in + (size_t)k * R_TOT);
    float4* ws4w = reinterpret_cast<float4*>(ws);
    for (int idx = tid; idx < 1024; idx += 256) ws4w[idx] = __ldg(&wk4[idx]);
    for (int idx = tid; idx < 512; idx += 256) {
        float4 v = __ldg(&ik4[idx]);
        int b = idx >> 4, i = (idx & 15) * 4;
        float* p = &as[b * 65 + i];
        p[0] = v.x; p[1] = v.y; p[2] = v.z; p[3] = v.w;
    }
    __syncthreads();

    int b2 = tid >> 4;   // 0..15
    int lg = tid & 15;   // 0..15
    const ulonglong2* wsu = reinterpret_cast<const ulonglong2*>(ws);
    u64 a0a = 0ull, a0b = 0ull, a1a = 0ull, a1b = 0ull;
#pragma unroll
    for (int i = 0; i < 64; i++) {
        float v0 = as[b2 * 65 + i];
        float v1 = as[(b2 + 16) * 65 + i];
        ulonglong2 w = wsu[i * 16 + lg];
        u64 p0 = pk2(v0, v0), p1 = pk2(v1, v1);
        a0a = ffma2(p0, w.x, a0a); a0b = ffma2(p0, w.y, a0b);
        a1a = ffma2(p1, w.x, a1a); a1b = ffma2(p1, w.y, a1b);
    }
    float2 e0 = up2(a0a), e1 = up2(a0b), e2 = up2(a1a), e3 = up2(a1b);
    float* ob = out + (size_t)k * R_TOT;
    *reinterpret_cast<float4*>(ob + b2 * 64 + lg * 4)        = make_float4(e0.x, e0.y, e1.x, e1.y);
    *reinterpret_cast<float4*>(ob + (b2 + 16) * 64 + lg * 4) = make_float4(e2.x, e2.y, e3.x, e3.y);
}

// ---------------------------------------------------------------------------
// K6: fused IDWT L4->3 + L3->2 per row (pair outputs via f32x2).
// ---------------------------------------------------------------------------
__global__ __launch_bounds__(256) void idwt432_kernel(const float* __restrict__ a4m,
                                                      const float* __restrict__ d4m,
                                                      const float* __restrict__ d3,
                                                      float* __restrict__ a2r) {
    __shared__ __align__(16) float sa4[520];
    __shared__ __align__(16) float sd4[520];
    __shared__ __align__(16) float sa3[1032];
    __shared__ __align__(16) float sd3[1032];
    int row = blockIdx.x, tid = threadIdx.x;
    const u64* lh = reinterpret_cast<const u64*>(c_lh);
    const float4* pa = reinterpret_cast<const float4*>(a4m + (size_t)row * M4P);
    const float4* pd = reinterpret_cast<const float4*>(d4m + (size_t)row * M4P);
    for (int i = tid; i < 130; i += 256) {
        *reinterpret_cast<float4*>(&sa4[4 * i]) = __ldg(&pa[i]);
        *reinterpret_cast<float4*>(&sd4[4 * i]) = __ldg(&pd[i]);
    }
    const float4* p3 = reinterpret_cast<const float4*>(d3 + (size_t)row * M3P);
    for (int i = tid; i < 258; i += 256)
        *reinterpret_cast<float4*>(&sd3[4 * i]) = __ldg(&p3[i]);
    __syncthreads();

    for (int q = tid; q < (M3 + 1) / 2; q += 256) {
        u64 accE = 0ull, accO = 0ull;
#pragma unroll
        for (int t = 0; t < 4; t++) {
            u64 ad = pk2(sa4[q + t], sd4[q + t]);
            accE = ffma2(ad, lh[2 * t + 1], accE);
            accO = ffma2(ad, lh[2 * t], accO);
        }
        float2 e = up2(accE), o = up2(accO);
        sa3[2 * q] = e.x + e.y;
        if (2 * q + 1 < M3) sa3[2 * q + 1] = o.x + o.y;
    }
    __syncthreads();

    float* outr = a2r + (size_t)row * M2P;
    for (int q = tid; q < (M2 + 1) / 2; q += 256) {
        u64 accE = 0ull, accO = 0ull;
#pragma unroll
        for (int t = 0; t < 4; t++) {
            u64 ad = pk2(sa3[q + t], sd3[q + t]);
            accE = ffma2(ad, lh[2 * t + 1], accE);
            accO = ffma2(ad, lh[2 * t], accO);
        }
        float2 e = up2(accE), o = up2(accO);
        outr[2 * q] = e.x + e.y;
        if (2 * q + 1 < M2) outr[2 * q + 1] = o.x + o.y;
    }
}

// ---------------------------------------------------------------------------
// K7: fused IDWT L2->1 + L1->0 + transpose-back + dense + mish.
// dk staged in SMEM (R11 config); dense tile = 4 rows x 4 channels so one
// 16B LDS of w feeds 16 FMAs.
// ---------------------------------------------------------------------------
__device__ __forceinline__ float mish_f(float v) {
    float sp = (v > 20.f) ? v : log1pf(expf(v));
    return v * tanhf(sp);
}

__global__ __launch_bounds__(256) void ifinal2_kernel(
    const float* __restrict__ a2r, const float* __restrict__ d2,
    const float* __restrict__ d1, const float* __restrict__ x,
    const float* __restrict__ dk, const float* __restrict__ bias,
    float* __restrict__ out) {
    extern __shared__ float sm[];
    float* dks = sm;            // 4096
    float* xs  = dks + 4096;    // 64*65 = 4160
    float* ys  = xs + 4160;     // 4160
    float* sA  = ys + 4160;     // 64*36 = 2304 (a1 recon window, 35 used)
    float* sD  = sA + 2304;     // 2304          (d1 window, 35 used)
    float* sA2 = sD + 2304;     // 64*22 = 1408 (21 used)
    float* sD2 = sA2 + 1408;    // 1408
    float* bs  = sD2 + 1408;    // 64
    // total 19904 floats = 79616 B

    int b = blockIdx.y;
    int n0 = blockIdx.x * 64;
    int r0 = n0 >> 1;   // even
    int q0 = r0 >> 1;
    int tid = threadIdx.x;
    const u64* lh = reinterpret_cast<const u64*>(c_lh);

    {   // dk via float4 into SMEM
        const float4* dk4g = reinterpret_cast<const float4*>(dk);
        float4* dks4 = reinterpret_cast<float4*>(dks);
        for (int idx = tid; idx < 1024; idx += 256) dks4[idx] = __ldg(&dk4g[idx]);
    }
    if (tid < 64) bs[tid] = __ldg(&bias[tid]);
    for (int idx = tid; idx < 64 * 21; idx += 256) {
        int c = idx / 21, i = idx - c * 21;
        size_t off = (size_t)(b * 64 + c) * M2P + q0 + i;
        sA2[c * 22 + i] = __ldg(&a2r[off]);
        sD2[c * 22 + i] = __ldg(&d2[off]);
    }
    for (int idx = tid; idx < 64 * 35; idx += 256) {
        int c = idx / 35, i = idx - c * 35;
        sD[c * 36 + i] = __ldg(&d1[(size_t)(b * 64 + c) * M1P + r0 + i]);
    }
    {   // x tile via float4: 64 nn x 16 groups
        const float4* xg = reinterpret_cast<const float4*>(x);
        for (int idx = tid; idx < 64 * 16; idx += 256) {
            int nn = idx >> 4, ig = idx & 15;
            float4 v = __ldg(&xg[((size_t)b * N0 + n0 + nn) * 16 + ig]);
            float* p = &xs[nn * 65 + ig * 4];
            p[0] = v.x; p[1] = v.y; p[2] = v.z; p[3] = v.w;
        }
    }
    __syncthreads();

    // reconstruct a1 window: pairs rr = 2m, 2m+1 (m = 0..17)
    for (int idx = tid; idx < 64 * 18; idx += 256) {
        int c = idx / 18, m = idx - c * 18;
        const float* A = &sA2[c * 22 + m];
        const float* D = &sD2[c * 22 + m];
        u64 accE = 0ull, accO = 0ull;
#pragma unroll
        for (int t = 0; t < 4; t++) {
            u64 ad = pk2(A[t], D[t]);
            accE = ffma2(ad, lh[2 * t + 1], accE);
            accO = ffma2(ad, lh[2 * t], accO);
        }
        float2 e = up2(accE), o = up2(accO);
        sA[c * 36 + 2 * m] = e.x + e.y;
        sA[c * 36 + 2 * m + 1] = o.x + o.y;
    }
    __syncthreads();

    // IDWT level 1 into ys[nn][c]: pairs nn = 2m, 2m+1 (m = 0..31)
    for (int idx = tid; idx < 64 * 32; idx += 256) {
        int c = idx >> 5, m = idx & 31;
        const float* A = &sA[c * 36 + m];
        const float* D = &sD[c * 36 + m];
        u64 accE = 0ull, accO = 0ull;
#pragma unroll
        for (int t = 0; t < 4; t++) {
            u64 ad = pk2(A[t], D[t]);
            accE = ffma2(ad, lh[2 * t + 1], accE);
            accO = ffma2(ad, lh[2 * t], accO);
        }
        float2 e = up2(accE), o = up2(accO);
        ys[(2 * m) * 65 + c] = e.x + e.y;
        ys[(2 * m + 1) * 65 + c] = o.x + o.y;
    }
    __syncthreads();

    // dense shortcut: thread = 4 rows {rb, rb+16, rb+32, rb+48} x 4 channels c..c+3
    int rb = tid >> 4;      // 0..15
    int lg = tid & 15;      // 0..15
    int c = lg * 4;
    const ulonglong2* dkw = reinterpret_cast<const ulonglong2*>(dks);
    u64 bi0 = pk2(bs[c], bs[c + 1]);
    u64 bi1 = pk2(bs[c + 2], bs[c + 3]);
    u64 acc[4][2];
#pragma unroll
    for (int h = 0; h < 4; h++) { acc[h][0] = bi0; acc[h][1] = bi1; }
#pragma unroll 4
    for (int i = 0; i < 64; i++) {
        ulonglong2 w = dkw[i * 16 + lg];   // 16B LDS shared by 4 rows
#pragma unroll
        for (int h = 0; h < 4; h++) {
            float xv = xs[(rb + h * 16) * 65 + i];
            u64 p = pk2(xv, xv);
            acc[h][0] = ffma2(p, w.x, acc[h][0]);
            acc[h][1] = ffma2(p, w.y, acc[h][1]);
        }
    }
#pragma unroll
    for (int h = 0; h < 4; h++) {
        int row = rb + h * 16;
        float2 e0 = up2(acc[h][0]), e1 = up2(acc[h][1]);
        float v[4] = {e0.x, e0.y, e1.x, e1.y};
#pragma unroll
        for (int u = 0; u < 4; u++)
            v[u] = mish_f(v[u] + ys[row * 65 + c + u]);
        *reinterpret_cast<float4*>(&out[((size_t)b * N0 + n0 + row) * CB + c]) =
            make_float4(v[0], v[1], v[2], v[3]);
    }
}

// ---------------------------------------------------------------------------
extern "C" void kernel_launch(void* const* d_in, const int* in_sizes, int n_in,
                              void* d_out, int out_size) {
    (void)in_sizes; (void)n_in; (void)out_size;
    const float* x    = (const float*)d_in[0];
    const float* w1   = (const float*)d_in[1];
    const float* w2   = (const float*)d_in[2];
    const float* dk   = (const float*)d_in[3];
    const float* bias = (const float*)d_in[4];
    float* out = (float*)d_out;

    float *d1, *a2, *d2, *d3, *a4, *d4;
    float *a4t, *d4t, *a4mt, *d4mt, *a4m, *d4m, *wt1, *wt2;
    cudaGetSymbolAddress((void**)&d1,   g_d1);
    cudaGetSymbolAddress((void**)&a2,   g_a2);
    cudaGetSymbolAddress((void**)&d2,   g_d2);
    cudaGetSymbolAddress((void**)&d3,   g_d3);
    cudaGetSymbolAddress((void**)&a4,   g_a4);
    cudaGetSymbolAddress((void**)&d4,   g_d4);
    cudaGetSymbolAddress((void**)&a4t,  g_a4t);
    cudaGetSymbolAddress((void**)&d4t,  g_d4t);
    cudaGetSymbolAddress((void**)&a4mt, g_a4mt);
    cudaGetSymbolAddress((void**)&d4mt, g_d4mt);
    cudaGetSymbolAddress((void**)&a4m,  g_a4m);
    cudaGetSymbolAddress((void**)&d4m,  g_d4m);
    cudaGetSymbolAddress((void**)&wt1,  g_wt1);
    cudaGetSymbolAddress((void**)&wt2,  g_wt2);

    const int K1_SMEM = (2 * 32 * 139 + 2 * 32 * 68) * (int)sizeof(float);  // 52992 B
    const int K7_SMEM = (4096 + 4160 + 4160 + 2304 + 2304 + 1408 + 1408 + 64) * (int)sizeof(float); // 79616 B
    cudaFuncSetAttribute(dwt12_kernel, cudaFuncAttributeMaxDynamicSharedMemorySize, K1_SMEM);
    cudaFuncSetAttribute(ifinal2_kernel, cudaFuncAttributeMaxDynamicSharedMemorySize, K7_SMEM);

    dim3 trb(32, 8);
    // 1. fused transpose + DWT L1 + L2
    dwt12_kernel<<<dim3(33, 64), 256, K1_SMEM>>>(x, d1, a2, d2);
    // 2. fused DWT L3 + L4
    dwt34_kernel<<<R_TOT, 256>>>(a2, d3, a4, d4);
    // 3. forward transposes
    tr4_kernel<<<dim3((M4 + 31) / 32, 4096 / 32, 4), trb>>>(a4, d4, w1, w2, a4t, d4t, wt1, wt2);
    // 4. channel mix
    mix_kernel<<<dim3(M4, 2), 256>>>(a4t, d4t, wt1, wt2, a4mt, d4mt);
    // 5. transpose mixed back
    tr2_kernel<<<dim3(R_TOT / 32, (M4 + 31) / 32, 2), trb>>>(a4mt, d4mt, a4m, d4m);
    // 6. fused IDWT L4->3->2
    idwt432_kernel<<<R_TOT, 256>>>(a4m, d4m, d3, a2);
    // 7. fused IDWT L2->1 + L1->0 + dense + mish
    ifinal2_kernel<<<dim3(N0 / 64, BB), 256, K7_SMEM>>>(a2, d2, d1, x, dk, bias, out);
}

// round 14
// speedup vs baseline: 1.0789x; 1.0789x over previous
#include <cuda_runtime.h>
#include <math.h>

#define R_TOT 2048   // B*C rows
#define N0 8192
#define M1 4099
#define M2 2053
#define M3 1030
#define M4 518
#define M1P 4100
#define M2P 2056
#define M3P 1032
#define M4P 520
#define CB 64
#define BB 32

__constant__ float c_dlo[8] = {-0.010597401784997278f, 0.032883011666982945f, 0.030841381835986965f,
                               -0.18703481171888114f, -0.02798376941698385f, 0.6308807679295904f,
                               0.7148465705525415f, 0.23037781330885523f};
__constant__ float c_dhi[8] = {-0.23037781330885523f, 0.7148465705525415f, -0.6308807679295904f,
                               -0.02798376941698385f, 0.18703481171888114f, 0.030841381835986965f,
                               -0.032883011666982945f, -0.010597401784997278f};
// packed (dlo[j], dhi[j]) pairs for f32x2 math
__constant__ float2 c_lh[8] = {
    {-0.010597401784997278f, -0.23037781330885523f},
    {0.032883011666982945f,  0.7148465705525415f},
    {0.030841381835986965f,  -0.6308807679295904f},
    {-0.18703481171888114f,  -0.02798376941698385f},
    {-0.02798376941698385f,  0.18703481171888114f},
    {0.6308807679295904f,    0.030841381835986965f},
    {0.7148465705525415f,    -0.032883011666982945f},
    {0.23037781330885523f,   -0.010597401784997278f}};

typedef unsigned long long u64;
__device__ __forceinline__ u64 ffma2(u64 a, u64 b, u64 c) {
    u64 d;
    asm("fma.rn.f32x2 %0, %1, %2, %3;" : "=l"(d) : "l"(a), "l"(b), "l"(c));
    return d;
}
__device__ __forceinline__ u64 pk2(float x, float y) {
    u64 r;
    asm("mov.b64 %0, {%1, %2};" : "=l"(r) : "f"(x), "f"(y));
    return r;
}
__device__ __forceinline__ float2 up2(u64 v) {
    float2 r;
    asm("mov.b64 {%0, %1}, %2;" : "=f"(r.x), "=f"(r.y) : "l"(v));
    return r;
}

// Scratch (static device globals; allocation-free per harness rules)
__device__ __align__(256) float g_d1[(size_t)R_TOT * M1P];
__device__ __align__(256) float g_a2[(size_t)R_TOT * M2P];   // fwd a2, later a2-recon
__device__ __align__(256) float g_d2[(size_t)R_TOT * M2P];
__device__ __align__(256) float g_d3[(size_t)R_TOT * M3P];
__device__ __align__(256) float g_a4[(size_t)R_TOT * M4P];
__device__ __align__(256) float g_d4[(size_t)R_TOT * M4P];
__device__ __align__(256) float g_a4t[(size_t)M4 * R_TOT];   // [k][row]
__device__ __align__(256) float g_d4t[(size_t)M4 * R_TOT];
__device__ __align__(256) float g_a4mt[(size_t)M4 * R_TOT];
__device__ __align__(256) float g_d4mt[(size_t)M4 * R_TOT];
__device__ __align__(256) float g_a4m[(size_t)R_TOT * M4P];  // [row][k]
__device__ __align__(256) float g_d4m[(size_t)R_TOT * M4P];
__device__ __align__(256) float g_wt1[(size_t)M4 * CB * CB]; // [k][i*64+o]
__device__ __align__(256) float g_wt2[(size_t)M4 * CB * CB];

// ---------------------------------------------------------------------------
// K1: fused transpose + DWT L1 + L2 (halo recompute). a1 only in SMEM.
// ---------------------------------------------------------------------------
__device__ __forceinline__ void dwt12_a1_body(
    int cc, int kk, int K0, int b, int c0,
    const float* __restrict__ xe, const float* __restrict__ xo,
    float* __restrict__ ae, float* __restrict__ ao,
    float* __restrict__ d1, const u64* __restrict__ lh) {
    int k1 = 2 * K0 - 6 + kk;
    if (k1 < 0 || k1 >= M1) return;
    const float* pe = &xe[cc * 139 + kk + 3];
    const float* po = &xo[cc * 139 + kk + 3];
    u64 acc = 0ull;
#pragma unroll
    for (int s = 0; s < 4; s++) {
        float vo = po[-s], ve = pe[-s];
        acc = ffma2(pk2(vo, vo), lh[2 * s], acc);
        acc = ffma2(pk2(ve, ve), lh[2 * s + 1], acc);
    }
    float2 ad = up2(acc);
    int tl = (k1 >> 1) - (K0 - 3);
    if (k1 & 1) ao[cc * 68 + tl] = ad.x;
    else        ae[cc * 68 + tl] = ad.x;
    if (kk >= 6) d1[(size_t)(b * 64 + c0 + cc) * M1P + k1] = ad.y;
}

__global__ __launch_bounds__(256) void dwt12_kernel(const float* __restrict__ x,
                                                    float* __restrict__ d1,
                                                    float* __restrict__ a2,
                                                    float* __restrict__ d2) {
    extern __shared__ float sm[];
    float* xe = sm;                 // [32][139]
    float* xo = sm + 32 * 139;      // [32][139]
    float* ae = sm + 2 * 32 * 139;  // [32][68]
    float* ao = ae + 32 * 68;       // [32][68]
    int K0 = blockIdx.x * 64;
    int ct = blockIdx.y;
    int b = ct >> 1, c0 = (ct & 1) * 32;
    int tid = threadIdx.x;
    int xbase = 4 * K0 - 18;        // even
    const u64* lh = reinterpret_cast<const u64*>(c_lh);

    // x window via float4 over channels: 276 rows x 8 cgroups
    for (int idx = tid; idx < 276 * 8; idx += 256) {
        int nn = idx >> 3, cg = idx & 7;
        int q = xbase + nn;
        q = (q < 0) ? (-1 - q) : q;
        q = (q >= N0) ? (2 * N0 - 1 - q) : q;
        float4 v = __ldg(reinterpret_cast<const float4*>(&x[((size_t)b * N0 + q) * CB + c0 + cg * 4]));
        int u = nn >> 1;
        float* dst = (nn & 1) ? xo : xe;
        int cb4 = cg * 4;
        dst[(cb4 + 0) * 139 + u] = v.x;
        dst[(cb4 + 1) * 139 + u] = v.y;
        dst[(cb4 + 2) * 139 + u] = v.z;
        dst[(cb4 + 3) * 139 + u] = v.w;
    }
    __syncthreads();

    // a1 window [2K0-6, 2K0+127] (kk 0..133): pow2 main loop + tail (no division)
    for (int idx = tid; idx < 32 * 128; idx += 256) {
        dwt12_a1_body(idx >> 7, idx & 127, K0, b, c0, xe, xo, ae, ao, d1, lh);
    }
    {   // tail kk 128..133
        int cc = tid >> 3, kk = 128 + (tid & 7);
        if (kk < 134) dwt12_a1_body(cc, kk, K0, b, c0, xe, xo, ae, ao, d1, lh);
    }
    __syncthreads();

    // level 2
    for (int idx = tid; idx < 32 * 64; idx += 256) {
        int cc = idx >> 6, kk2 = idx & 63;
        int k2 = K0 + kk2;
        if (k2 >= M2) continue;
        float sa, sd;
        if (k2 >= 3 && k2 <= 2048) {
            const float* pe = &ae[cc * 68 + kk2 + 3];
            const float* po = &ao[cc * 68 + kk2 + 3];
            u64 acc = 0ull;
#pragma unroll
            for (int s = 0; s < 4; s++) {
                float vo = po[-s], ve = pe[-s];
                acc = ffma2(pk2(vo, vo), lh[2 * s], acc);
                acc = ffma2(pk2(ve, ve), lh[2 * s + 1], acc);
            }
            float2 ad = up2(acc);
            sa = ad.x; sd = ad.y;
        } else {
            sa = 0.f; sd = 0.f;
#pragma unroll
            for (int j = 0; j < 8; j++) {
                int g = 2 * k2 + 1 - j;
                g = (g < 0) ? (-1 - g) : g;
                g = (g >= M1) ? (2 * M1 - 1 - g) : g;
                int tl = (g >> 1) - (K0 - 3);
                float v = (g & 1) ? ao[cc * 68 + tl] : ae[cc * 68 + tl];
                sa = fmaf(v, c_dlo[j], sa);
                sd = fmaf(v, c_dhi[j], sd);
            }
        }
        size_t off = (size_t)(b * 64 + c0 + cc) * M2P + k2;
        a2[off] = sa;
        d2[off] = sd;
    }
}

// ---------------------------------------------------------------------------
// K2: fused DWT L3 + L4 per row. a3 only in SMEM.
// ---------------------------------------------------------------------------
__global__ __launch_bounds__(256) void dwt34_kernel(const float* __restrict__ a2,
                                                    float* __restrict__ d3,
                                                    float* __restrict__ a4,
                                                    float* __restrict__ d4) {
    __shared__ __align__(16) float s2e[1032];
    __shared__ __align__(16) float s2o[1032];
    __shared__ __align__(16) float a3e[520];
    __shared__ __align__(16) float a3o[520];
    int row = blockIdx.x, tid = threadIdx.x;
    const u64* lh = reinterpret_cast<const u64*>(c_lh);
    const float4* s4 = reinterpret_cast<const float4*>(a2 + (size_t)row * M2P);
    for (int i = tid; i < 514; i += 256) {
        float4 v = __ldg(&s4[i]);
        int u = 2 * i;
        s2e[u] = v.x; s2o[u] = v.y; s2e[u + 1] = v.z; s2o[u + 1] = v.w;
    }
    __syncthreads();
    float* d3r = d3 + (size_t)row * M3P;
    for (int k = tid; k < M3; k += 256) {
        float sa, sd;
        if (k >= 3 && k <= 1025) {
            u64 acc = 0ull;
#pragma unroll
            for (int s = 0; s < 4; s++) {
                float vo = s2o[k - s], ve = s2e[k - s];
                acc = ffma2(pk2(vo, vo), lh[2 * s], acc);
                acc = ffma2(pk2(ve, ve), lh[2 * s + 1], acc);
            }
            float2 ad = up2(acc);
            sa = ad.x; sd = ad.y;
        } else {
            sa = 0.f; sd = 0.f;
#pragma unroll
            for (int j = 0; j < 8; j++) {
                int g = 2 * k + 1 - j;
                g = (g < 0) ? (-1 - g) : g;
                g = (g >= M2) ? (2 * M2 - 1 - g) : g;
                float v = (g & 1) ? s2o[g >> 1] : s2e[g >> 1];
                sa = fmaf(v, c_dlo[j], sa);
                sd = fmaf(v, c_dhi[j], sd);
            }
        }
        if (k & 1) a3o[k >> 1] = sa; else a3e[k >> 1] = sa;
        d3r[k] = sd;
    }
    __syncthreads();
    float* a4r = a4 + (size_t)row * M4P;
    float* d4r = d4 + (size_t)row * M4P;
    for (int k = tid; k < M4; k += 256) {
        float sa, sd;
        if (k >= 3 && k <= 514) {
            u64 acc = 0ull;
#pragma unroll
            for (int s = 0; s < 4; s++) {
                float vo = a3o[k - s], ve = a3e[k - s];
                acc = ffma2(pk2(vo, vo), lh[2 * s], acc);
                acc = ffma2(pk2(ve, ve), lh[2 * s + 1], acc);
            }
            float2 ad = up2(acc);
            sa = ad.x; sd = ad.y;
        } else {
            sa = 0.f; sd = 0.f;
#pragma unroll
            for (int j = 0; j < 8; j++) {
                int g = 2 * k + 1 - j;
                g = (g < 0) ? (-1 - g) : g;
                g = (g >= M3) ? (2 * M3 - 1 - g) : g;
                float v = (g & 1) ? a3o[g >> 1] : a3e[g >> 1];
                sa = fmaf(v, c_dlo[j], sa);
                sd = fmaf(v, c_dhi[j], sd);
            }
        }
        a4r[k] = sa;
        d4r[k] = sd;
    }
}

// ---------------------------------------------------------------------------
// Forward transposes (z=0: a4->a4t, 1: d4->d4t, 2: w1->wt1, 3: w2->wt2)
// ---------------------------------------------------------------------------
__global__ void tr4_kernel(const float* __restrict__ s0, const float* __restrict__ s1,
                           const float* __restrict__ s2, const float* __restrict__ s3,
                           float* __restrict__ o0, float* __restrict__ o1,
                           float* __restrict__ o2, float* __restrict__ o3) {
    __shared__ float tile[32][33];
    int z = blockIdx.z;
    const float* __restrict__ src; float* __restrict__ dst; int R, ss, ds;
    if (z == 0)      { src = s0; dst = o0; R = R_TOT; ss = M4P; ds = R_TOT; }
    else if (z == 1) { src = s1; dst = o1; R = R_TOT; ss = M4P; ds = R_TOT; }
    else if (z == 2) { src = s2; dst = o2; R = 4096;  ss = M4;  ds = 4096; }
    else             { src = s3; dst = o3; R = 4096;  ss = M4;  ds = 4096; }
    int c0 = blockIdx.x * 32;
    int r0 = blockIdx.y * 32;
    if (r0 >= R) return;
    int tx = threadIdx.x, ty = threadIdx.y;
#pragma unroll
    for (int i = 0; i < 32; i += 8) {
        int r = r0 + ty + i, c = c0 + tx;
        if (r < R && c < M4) tile[ty + i][tx] = src[(size_t)r * ss + c];
    }
    __syncthreads();
#pragma unroll
    for (int i = 0; i < 32; i += 8) {
        int c = c0 + ty + i, r = r0 + tx;
        if (c < M4 && r < R) dst[(size_t)c * ds + r] = tile[tx][ty + i];
    }
}

// ---------------------------------------------------------------------------
// Back transposes (z=0: a4mt->a4m, 1: d4mt->d4m)
// ---------------------------------------------------------------------------
__global__ void tr2_kernel(const float* __restrict__ s0, const float* __restrict__ s1,
                           float* __restrict__ o0, float* __restrict__ o1) {
    __shared__ float tile[32][33];
    const float* __restrict__ src = blockIdx.z ? s1 : s0;
    float* __restrict__ dst = blockIdx.z ? o1 : o0;
    int c0 = blockIdx.x * 32;
    int r0 = blockIdx.y * 32;
    int tx = threadIdx.x, ty = threadIdx.y;
#pragma unroll
    for (int i = 0; i < 32; i += 8) {
        int r = r0 + ty + i;
        if (r < M4) tile[ty + i][tx] = src[(size_t)r * R_TOT + c0 + tx];
    }
    __syncthreads();
#pragma unroll
    for (int i = 0; i < 32; i += 8) {
        int r = r0 + tx;
        if (r < M4) dst[(size_t)(c0 + ty + i) * M4P + r] = tile[tx][ty + i];
    }
}

// ---------------------------------------------------------------------------
// Channel mix: 2 batches per thread share each w load; f32x2 accumulate. (R12 WIN)
// ---------------------------------------------------------------------------
__global__ __launch_bounds__(256) void mix_kernel(
    const float* __restrict__ a4t, const float* __restrict__ d4t,
    const float* __restrict__ wt1, const float* __restrict__ wt2,
    float* __restrict__ a4mt, float* __restrict__ d4mt) {
    int k = blockIdx.x;
    const float* __restrict__ in = blockIdx.y ? d4t : a4t;
    const float* __restrict__ wt = blockIdx.y ? wt2 : wt1;
    float* __restrict__ out = blockIdx.y ? d4mt : a4mt;

    __shared__ __align__(16) float ws[4096];
    __shared__ float as[32 * 65];
    int tid = threadIdx.x;
    const float4* __restrict__ wk4 = reinterpret_cast<const float4*>(wt + (size_t)k * 4096);
    const float4* __restrict__ ik4 = reinterpret_cast<const float4*>(in + (size_t)k * R_TOT);
    float4* ws4w = reinterpret_cast<float4*>(ws);
    for (int idx = tid; idx < 1024; idx += 256) ws4w[idx] = __ldg(&wk4[idx]);
    for (int idx = tid; idx < 512; idx += 256) {
        float4 v = __ldg(&ik4[idx]);
        int b = idx >> 4, i = (idx & 15) * 4;
        float* p = &as[b * 65 + i];
        p[0] = v.x; p[1] = v.y; p[2] = v.z; p[3] = v.w;
    }
    __syncthreads();

    int b2 = tid >> 4;   // 0..15
    int lg = tid & 15;   // 0..15
    const ulonglong2* wsu = reinterpret_cast<const ulonglong2*>(ws);
    u64 a0a = 0ull, a0b = 0ull, a1a = 0ull, a1b = 0ull;
#pragma unroll
    for (int i = 0; i < 64; i++) {
        float v0 = as[b2 * 65 + i];
        float v1 = as[(b2 + 16) * 65 + i];
        ulonglong2 w = wsu[i * 16 + lg];
        u64 p0 = pk2(v0, v0), p1 = pk2(v1, v1);
        a0a = ffma2(p0, w.x, a0a); a0b = ffma2(p0, w.y, a0b);
        a1a = ffma2(p1, w.x, a1a); a1b = ffma2(p1, w.y, a1b);
    }
    float2 e0 = up2(a0a), e1 = up2(a0b), e2 = up2(a1a), e3 = up2(a1b);
    float* ob = out + (size_t)k * R_TOT;
    *reinterpret_cast<float4*>(ob + b2 * 64 + lg * 4)        = make_float4(e0.x, e0.y, e1.x, e1.y);
    *reinterpret_cast<float4*>(ob + (b2 + 16) * 64 + lg * 4) = make_float4(e2.x, e2.y, e3.x, e3.y);
}

// ---------------------------------------------------------------------------
// K6: fused IDWT L4->3 + L3->2 per row (pair outputs via f32x2).
// ---------------------------------------------------------------------------
__global__ __launch_bounds__(256) void idwt432_kernel(const float* __restrict__ a4m,
                                                      const float* __restrict__ d4m,
                                                      const float* __restrict__ d3,
                                                      float* __restrict__ a2r) {
    __shared__ __align__(16) float sa4[520];
    __shared__ __align__(16) float sd4[520];
    __shared__ __align__(16) float sa3[1032];
    __shared__ __align__(16) float sd3[1032];
    int row = blockIdx.x, tid = threadIdx.x;
    const u64* lh = reinterpret_cast<const u64*>(c_lh);
    const float4* pa = reinterpret_cast<const float4*>(a4m + (size_t)row * M4P);
    const float4* pd = reinterpret_cast<const float4*>(d4m + (size_t)row * M4P);
    for (int i = tid; i < 130; i += 256) {
        *reinterpret_cast<float4*>(&sa4[4 * i]) = __ldg(&pa[i]);
        *reinterpret_cast<float4*>(&sd4[4 * i]) = __ldg(&pd[i]);
    }
    const float4* p3 = reinterpret_cast<const float4*>(d3 + (size_t)row * M3P);
    for (int i = tid; i < 258; i += 256)
        *reinterpret_cast<float4*>(&sd3[4 * i]) = __ldg(&p3[i]);
    __syncthreads();

    for (int q = tid; q < (M3 + 1) / 2; q += 256) {
        u64 accE = 0ull, accO = 0ull;
#pragma unroll
        for (int t = 0; t < 4; t++) {
            u64 ad = pk2(sa4[q + t], sd4[q + t]);
            accE = ffma2(ad, lh[2 * t + 1], accE);
            accO = ffma2(ad, lh[2 * t], accO);
        }
        float2 e = up2(accE), o = up2(accO);
        sa3[2 * q] = e.x + e.y;
        if (2 * q + 1 < M3) sa3[2 * q + 1] = o.x + o.y;
    }
    __syncthreads();

    float* outr = a2r + (size_t)row * M2P;
    for (int q = tid; q < (M2 + 1) / 2; q += 256) {
        u64 accE = 0ull, accO = 0ull;
#pragma unroll
        for (int t = 0; t < 4; t++) {
            u64 ad = pk2(sa3[q + t], sd3[q + t]);
            accE = ffma2(ad, lh[2 * t + 1], accE);
            accO = ffma2(ad, lh[2 * t], accO);
        }
        float2 e = up2(accE), o = up2(accO);
        outr[2 * q] = e.x + e.y;
        if (2 * q + 1 < M2) outr[2 * q + 1] = o.x + o.y;
    }
}

// ---------------------------------------------------------------------------
// K7: fused IDWT L2->1 + L1->0 + transpose-back + dense (f32x2) + mish.
// EXACT round-11 configuration (343 us): dk staged in SMEM, dense thread =
// 2 rows (nn, nn+32) x 8 channels, lg = tid&7 (conflict-free LDS).
// ---------------------------------------------------------------------------
__device__ __forceinline__ float mish_f(float v) {
    float sp = (v > 20.f) ? v : log1pf(expf(v));
    return v * tanhf(sp);
}

__global__ __launch_bounds__(256) void ifinal2_kernel(
    const float* __restrict__ a2r, const float* __restrict__ d2,
    const float* __restrict__ d1, const float* __restrict__ x,
    const float* __restrict__ dk, const float* __restrict__ bias,
    float* __restrict__ out) {
    extern __shared__ float sm[];
    float* dks = sm;            // 4096
    float* xs  = dks + 4096;    // 64*65 = 4160
    float* ys  = xs + 4160;     // 4160
    float* sA  = ys + 4160;     // 64*36 = 2304 (a1 recon window, 35 used)
    float* sD  = sA + 2304;     // 2304          (d1 window, 35 used)
    float* sA2 = sD + 2304;     // 64*22 = 1408 (21 used)
    float* sD2 = sA2 + 1408;    // 1408
    float* bs  = sD2 + 1408;    // 64

    int b = blockIdx.y;
    int n0 = blockIdx.x * 64;
    int r0 = n0 >> 1;   // even
    int q0 = r0 >> 1;
    int tid = threadIdx.x;
    const u64* lh = reinterpret_cast<const u64*>(c_lh);

    {   // dk via float4
        const float4* dk4g = reinterpret_cast<const float4*>(dk);
        float4* dks4 = reinterpret_cast<float4*>(dks);
        for (int idx = tid; idx < 1024; idx += 256) dks4[idx] = __ldg(&dk4g[idx]);
    }
    if (tid < 64) bs[tid] = __ldg(&bias[tid]);
    for (int idx = tid; idx < 64 * 21; idx += 256) {
        int c = idx / 21, i = idx - c * 21;
        size_t off = (size_t)(b * 64 + c) * M2P + q0 + i;
        sA2[c * 22 + i] = __ldg(&a2r[off]);
        sD2[c * 22 + i] = __ldg(&d2[off]);
    }
    for (int idx = tid; idx < 64 * 35; idx += 256) {
        int c = idx / 35, i = idx - c * 35;
        sD[c * 36 + i] = __ldg(&d1[(size_t)(b * 64 + c) * M1P + r0 + i]);
    }
    {   // x tile via float4: 64 nn x 16 groups
        const float4* xg = reinterpret_cast<const float4*>(x);
        for (int idx = tid; idx < 64 * 16; idx += 256) {
            int nn = idx >> 4, ig = idx & 15;
            float4 v = __ldg(&xg[((size_t)b * N0 + n0 + nn) * 16 + ig]);
            float* p = &xs[nn * 65 + ig * 4];
            p[0] = v.x; p[1] = v.y; p[2] = v.z; p[3] = v.w;
        }
    }
    __syncthreads();

    // reconstruct a1 window: pairs rr = 2m, 2m+1 (m = 0..17)
    for (int idx = tid; idx < 64 * 18; idx += 256) {
        int c = idx / 18, m = idx - c * 18;
        const float* A = &sA2[c * 22 + m];
        const float* D = &sD2[c * 22 + m];
        u64 accE = 0ull, accO = 0ull;
#pragma unroll
        for (int t = 0; t < 4; t++) {
            u64 ad = pk2(A[t], D[t]);
            accE = ffma2(ad, lh[2 * t + 1], accE);
            accO = ffma2(ad, lh[2 * t], accO);
        }
        float2 e = up2(accE), o = up2(accO);
        sA[c * 36 + 2 * m] = e.x + e.y;
        sA[c * 36 + 2 * m + 1] = o.x + o.y;
    }
    __syncthreads();

    // IDWT level 1 into ys[nn][c]: pairs nn = 2m, 2m+1 (m = 0..31)
    for (int idx = tid; idx < 64 * 32; idx += 256) {
        int c = idx >> 5, m = idx & 31;
        const float* A = &sA[c * 36 + m];
        const float* D = &sD[c * 36 + m];
        u64 accE = 0ull, accO = 0ull;
#pragma unroll
        for (int t = 0; t < 4; t++) {
            u64 ad = pk2(A[t], D[t]);
            accE = ffma2(ad, lh[2 * t + 1], accE);
            accO = ffma2(ad, lh[2 * t], accO);
        }
        float2 e = up2(accE), o = up2(accO);
        ys[(2 * m) * 65 + c] = e.x + e.y;
        ys[(2 * m + 1) * 65 + c] = o.x + o.y;
    }
    __syncthreads();

    // dense shortcut (f32x2) + add + mish; thread: 2 nn (nn, nn+32) x 8 c
    int nn = tid >> 3;
    int lg = tid & 7;
    int g = lg * 4;
    const ulonglong2* dk2 = reinterpret_cast<const ulonglong2*>(dks);
    u64 bi0 = pk2(bs[g], bs[g + 1]);
    u64 bi1 = pk2(bs[g + 2], bs[g + 3]);
    u64 bi2 = pk2(bs[g + 32], bs[g + 33]);
    u64 bi3 = pk2(bs[g + 34], bs[g + 35]);
    u64 a00 = bi0, a01 = bi1, a02 = bi2, a03 = bi3;
    u64 a10 = bi0, a11 = bi1, a12 = bi2, a13 = bi3;
#pragma unroll
    for (int i = 0; i < 64; i++) {
        float xv0 = xs[nn * 65 + i];
        float xv1 = xs[(nn + 32) * 65 + i];
        u64 p0 = pk2(xv0, xv0), p1 = pk2(xv1, xv1);
        ulonglong2 w0 = dk2[i * 16 + lg];
        ulonglong2 w1 = dk2[i * 16 + 8 + lg];
        a00 = ffma2(p0, w0.x, a00); a01 = ffma2(p0, w0.y, a01);
        a02 = ffma2(p0, w1.x, a02); a03 = ffma2(p0, w1.y, a03);
        a10 = ffma2(p1, w0.x, a10); a11 = ffma2(p1, w0.y, a11);
        a12 = ffma2(p1, w1.x, a12); a13 = ffma2(p1, w1.y, a13);
    }
#pragma unroll
    for (int h = 0; h < 2; h++) {
        int row = nn + h * 32;
        float2 q0_ = up2(h ? a10 : a00), q1_ = up2(h ? a11 : a01);
        float2 q2_ = up2(h ? a12 : a02), q3_ = up2(h ? a13 : a03);
        float v0[4] = {q0_.x, q0_.y, q1_.x, q1_.y};
        float v1[4] = {q2_.x, q2_.y, q3_.x, q3_.y};
#pragma unroll
        for (int u = 0; u < 4; u++) {
            v0[u] = mish_f(v0[u] + ys[row * 65 + g + u]);
            v1[u] = mish_f(v1[u] + ys[row * 65 + g + 32 + u]);
        }
        float4* op = reinterpret_cast<float4*>(&out[((size_t)b * N0 + n0 + row) * CB]);
        op[lg] = make_float4(v0[0], v0[1], v0[2], v0[3]);
        op[8 + lg] = make_float4(v1[0], v1[1], v1[2], v1[3]);
    }
}

// ---------------------------------------------------------------------------
extern "C" void kernel_launch(void* const* d_in, const int* in_sizes, int n_in,
                              void* d_out, int out_size) {
    (void)in_sizes; (void)n_in; (void)out_size;
    const float* x    = (const float*)d_in[0];
    const float* w1   = (const float*)d_in[1];
    const float* w2   = (const float*)d_in[2];
    const float* dk   = (const float*)d_in[3];
    const float* bias = (const float*)d_in[4];
    float* out = (float*)d_out;

    float *d1, *a2, *d2, *d3, *a4, *d4;
    float *a4t, *d4t, *a4mt, *d4mt, *a4m, *d4m, *wt1, *wt2;
    cudaGetSymbolAddress((void**)&d1,   g_d1);
    cudaGetSymbolAddress((void**)&a2,   g_a2);
    cudaGetSymbolAddress((void**)&d2,   g_d2);
    cudaGetSymbolAddress((void**)&d3,   g_d3);
    cudaGetSymbolAddress((void**)&a4,   g_a4);
    cudaGetSymbolAddress((void**)&d4,   g_d4);
    cudaGetSymbolAddress((void**)&a4t,  g_a4t);
    cudaGetSymbolAddress((void**)&d4t,  g_d4t);
    cudaGetSymbolAddress((void**)&a4mt, g_a4mt);
    cudaGetSymbolAddress((void**)&d4mt, g_d4mt);
    cudaGetSymbolAddress((void**)&a4m,  g_a4m);
    cudaGetSymbolAddress((void**)&d4m,  g_d4m);
    cudaGetSymbolAddress((void**)&wt1,  g_wt1);
    cudaGetSymbolAddress((void**)&wt2,  g_wt2);

    const int K1_SMEM = (2 * 32 * 139 + 2 * 32 * 68) * (int)sizeof(float);  // 52992 B
    const int K7_SMEM = (4096 + 4160 + 4160 + 2304 + 2304 + 1408 + 1408 + 64) * (int)sizeof(float); // 79616 B
    cudaFuncSetAttribute(dwt12_kernel, cudaFuncAttributeMaxDynamicSharedMemorySize, K1_SMEM);
    cudaFuncSetAttribute(ifinal2_kernel, cudaFuncAttributeMaxDynamicSharedMemorySize, K7_SMEM);

    dim3 trb(32, 8);
    // 1. fused transpose + DWT L1 + L2
    dwt12_kernel<<<dim3(33, 64), 256, K1_SMEM>>>(x, d1, a2, d2);
    // 2. fused DWT L3 + L4
    dwt34_kernel<<<R_TOT, 256>>>(a2, d3, a4, d4);
    // 3. forward transposes
    tr4_kernel<<<dim3((M4 + 31) / 32, 4096 / 32, 4), trb>>>(a4, d4, w1, w2, a4t, d4t, wt1, wt2);
    // 4. channel mix
    mix_kernel<<<dim3(M4, 2), 256>>>(a4t, d4t, wt1, wt2, a4mt, d4mt);
    // 5. transpose mixed back
    tr2_kernel<<<dim3(R_TOT / 32, (M4 + 31) / 32, 2), trb>>>(a4mt, d4mt, a4m, d4m);
    // 6. fused IDWT L4->3->2
    idwt432_kernel<<<R_TOT, 256>>>(a4m, d4m, d3, a2);
    // 7. fused IDWT L2->1 + L1->0 + dense + mish (R11 config)
    ifinal2_kernel<<<dim3(N0 / 64, BB), 256, K7_SMEM>>>(a2, d2, d1, x, dk, bias, out);
}

// round 15
// speedup vs baseline: 1.1334x; 1.0505x over previous
#include <cuda_runtime.h>
#include <math.h>

#define R_TOT 2048   // B*C rows
#define N0 8192
#define M1 4099
#define M2 2053
#define M3 1030
#define M4 518
#define M1P 4100
#define M2P 2056
#define M3P 1032
#define M4P 520
#define CB 64
#define BB 32

__constant__ float c_dlo[8] = {-0.010597401784997278f, 0.032883011666982945f, 0.030841381835986965f,
                               -0.18703481171888114f, -0.02798376941698385f, 0.6308807679295904f,
                               0.7148465705525415f, 0.23037781330885523f};
__constant__ float c_dhi[8] = {-0.23037781330885523f, 0.7148465705525415f, -0.6308807679295904f,
                               -0.02798376941698385f, 0.18703481171888114f, 0.030841381835986965f,
                               -0.032883011666982945f, -0.010597401784997278f};
// packed (dlo[j], dhi[j]) pairs for f32x2 math
__constant__ float2 c_lh[8] = {
    {-0.010597401784997278f, -0.23037781330885523f},
    {0.032883011666982945f,  0.7148465705525415f},
    {0.030841381835986965f,  -0.6308807679295904f},
    {-0.18703481171888114f,  -0.02798376941698385f},
    {-0.02798376941698385f,  0.18703481171888114f},
    {0.6308807679295904f,    0.030841381835986965f},
    {0.7148465705525415f,    -0.032883011666982945f},
    {0.23037781330885523f,   -0.010597401784997278f}};

typedef unsigned long long u64;
__device__ __forceinline__ u64 ffma2(u64 a, u64 b, u64 c) {
    u64 d;
    asm("fma.rn.f32x2 %0, %1, %2, %3;" : "=l"(d) : "l"(a), "l"(b), "l"(c));
    return d;
}
__device__ __forceinline__ u64 pk2(float x, float y) {
    u64 r;
    asm("mov.b64 %0, {%1, %2};" : "=l"(r) : "f"(x), "f"(y));
    return r;
}
__device__ __forceinline__ float2 up2(u64 v) {
    float2 r;
    asm("mov.b64 {%0, %1}, %2;" : "=f"(r.x), "=f"(r.y) : "l"(v));
    return r;
}

// Scratch (static device globals; allocation-free per harness rules)
__device__ __align__(256) float g_d1[(size_t)R_TOT * M1P];
__device__ __align__(256) float g_a2[(size_t)R_TOT * M2P];   // fwd a2, later a2-recon
__device__ __align__(256) float g_d2[(size_t)R_TOT * M2P];
__device__ __align__(256) float g_d3[(size_t)R_TOT * M3P];
__device__ __align__(256) float g_a4[(size_t)R_TOT * M4P];
__device__ __align__(256) float g_d4[(size_t)R_TOT * M4P];
__device__ __align__(256) float g_a4t[(size_t)M4 * R_TOT];   // [k][row]
__device__ __align__(256) float g_d4t[(size_t)M4 * R_TOT];
__device__ __align__(256) float g_a4mt[(size_t)M4 * R_TOT];
__device__ __align__(256) float g_d4mt[(size_t)M4 * R_TOT];
__device__ __align__(256) float g_a4m[(size_t)R_TOT * M4P];  // [row][k]
__device__ __align__(256) float g_d4m[(size_t)R_TOT * M4P];
__device__ __align__(256) float g_wt1[(size_t)M4 * CB * CB]; // [k][i*64+o]
__device__ __align__(256) float g_wt2[(size_t)M4 * CB * CB];

// ---------------------------------------------------------------------------
// K1: fused transpose + DWT L1 + L2 (halo recompute). a1 only in SMEM.
// ---------------------------------------------------------------------------
__device__ __forceinline__ void dwt12_a1_body(
    int cc, int kk, int K0, int b, int c0,
    const float* __restrict__ xe, const float* __restrict__ xo,
    float* __restrict__ ae, float* __restrict__ ao,
    float* __restrict__ d1, const u64* __restrict__ lh) {
    int k1 = 2 * K0 - 6 + kk;
    if (k1 < 0 || k1 >= M1) return;
    const float* pe = &xe[cc * 139 + kk + 3];
    const float* po = &xo[cc * 139 + kk + 3];
    u64 acc = 0ull;
#pragma unroll
    for (int s = 0; s < 4; s++) {
        float vo = po[-s], ve = pe[-s];
        acc = ffma2(pk2(vo, vo), lh[2 * s], acc);
        acc = ffma2(pk2(ve, ve), lh[2 * s + 1], acc);
    }
    float2 ad = up2(acc);
    int tl = (k1 >> 1) - (K0 - 3);
    if (k1 & 1) ao[cc * 68 + tl] = ad.x;
    else        ae[cc * 68 + tl] = ad.x;
    if (kk >= 6) d1[(size_t)(b * 64 + c0 + cc) * M1P + k1] = ad.y;
}

__global__ __launch_bounds__(256) void dwt12_kernel(const float* __restrict__ x,
                                                    float* __restrict__ d1,
                                                    float* __restrict__ a2,
                                                    float* __restrict__ d2) {
    extern __shared__ float sm[];
    float* xe = sm;                 // [32][139]
    float* xo = sm + 32 * 139;      // [32][139]
    float* ae = sm + 2 * 32 * 139;  // [32][68]
    float* ao = ae + 32 * 68;       // [32][68]
    int K0 = blockIdx.x * 64;
    int ct = blockIdx.y;
    int b = ct >> 1, c0 = (ct & 1) * 32;
    int tid = threadIdx.x;
    int xbase = 4 * K0 - 18;        // even
    const u64* lh = reinterpret_cast<const u64*>(c_lh);

    // x window via float4 over channels: 276 rows x 8 cgroups
    for (int idx = tid; idx < 276 * 8; idx += 256) {
        int nn = idx >> 3, cg = idx & 7;
        int q = xbase + nn;
        q = (q < 0) ? (-1 - q) : q;
        q = (q >= N0) ? (2 * N0 - 1 - q) : q;
        float4 v = __ldg(reinterpret_cast<const float4*>(&x[((size_t)b * N0 + q) * CB + c0 + cg * 4]));
        int u = nn >> 1;
        float* dst = (nn & 1) ? xo : xe;
        int cb4 = cg * 4;
        dst[(cb4 + 0) * 139 + u] = v.x;
        dst[(cb4 + 1) * 139 + u] = v.y;
        dst[(cb4 + 2) * 139 + u] = v.z;
        dst[(cb4 + 3) * 139 + u] = v.w;
    }
    __syncthreads();

    // a1 window [2K0-6, 2K0+127] (kk 0..133): pow2 main loop + tail (no division)
    for (int idx = tid; idx < 32 * 128; idx += 256) {
        dwt12_a1_body(idx >> 7, idx & 127, K0, b, c0, xe, xo, ae, ao, d1, lh);
    }
    {   // tail kk 128..133
        int cc = tid >> 3, kk = 128 + (tid & 7);
        if (kk < 134) dwt12_a1_body(cc, kk, K0, b, c0, xe, xo, ae, ao, d1, lh);
    }
    __syncthreads();

    // level 2
    for (int idx = tid; idx < 32 * 64; idx += 256) {
        int cc = idx >> 6, kk2 = idx & 63;
        int k2 = K0 + kk2;
        if (k2 >= M2) continue;
        float sa, sd;
        if (k2 >= 3 && k2 <= 2048) {
            const float* pe = &ae[cc * 68 + kk2 + 3];
            const float* po = &ao[cc * 68 + kk2 + 3];
            u64 acc = 0ull;
#pragma unroll
            for (int s = 0; s < 4; s++) {
                float vo = po[-s], ve = pe[-s];
                acc = ffma2(pk2(vo, vo), lh[2 * s], acc);
                acc = ffma2(pk2(ve, ve), lh[2 * s + 1], acc);
            }
            float2 ad = up2(acc);
            sa = ad.x; sd = ad.y;
        } else {
            sa = 0.f; sd = 0.f;
#pragma unroll
            for (int j = 0; j < 8; j++) {
                int g = 2 * k2 + 1 - j;
                g = (g < 0) ? (-1 - g) : g;
                g = (g >= M1) ? (2 * M1 - 1 - g) : g;
                int tl = (g >> 1) - (K0 - 3);
                float v = (g & 1) ? ao[cc * 68 + tl] : ae[cc * 68 + tl];
                sa = fmaf(v, c_dlo[j], sa);
                sd = fmaf(v, c_dhi[j], sd);
            }
        }
        size_t off = (size_t)(b * 64 + c0 + cc) * M2P + k2;
        a2[off] = sa;
        d2[off] = sd;
    }
}

// ---------------------------------------------------------------------------
// K2: fused DWT L3 + L4 per row. a3 only in SMEM.
// ---------------------------------------------------------------------------
__global__ __launch_bounds__(256) void dwt34_kernel(const float* __restrict__ a2,
                                                    float* __restrict__ d3,
                                                    float* __restrict__ a4,
                                                    float* __restrict__ d4) {
    __shared__ __align__(16) float s2e[1032];
    __shared__ __align__(16) float s2o[1032];
    __shared__ __align__(16) float a3e[520];
    __shared__ __align__(16) float a3o[520];
    int row = blockIdx.x, tid = threadIdx.x;
    const u64* lh = reinterpret_cast<const u64*>(c_lh);
    const float4* s4 = reinterpret_cast<const float4*>(a2 + (size_t)row * M2P);
    for (int i = tid; i < 514; i += 256) {
        float4 v = __ldg(&s4[i]);
        int u = 2 * i;
        s2e[u] = v.x; s2o[u] = v.y; s2e[u + 1] = v.z; s2o[u + 1] = v.w;
    }
    __syncthreads();
    float* d3r = d3 + (size_t)row * M3P;
    for (int k = tid; k < M3; k += 256) {
        float sa, sd;
        if (k >= 3 && k <= 1025) {
            u64 acc = 0ull;
#pragma unroll
            for (int s = 0; s < 4; s++) {
                float vo = s2o[k - s], ve = s2e[k - s];
                acc = ffma2(pk2(vo, vo), lh[2 * s], acc);
                acc = ffma2(pk2(ve, ve), lh[2 * s + 1], acc);
            }
            float2 ad = up2(acc);
            sa = ad.x; sd = ad.y;
        } else {
            sa = 0.f; sd = 0.f;
#pragma unroll
            for (int j = 0; j < 8; j++) {
                int g = 2 * k + 1 - j;
                g = (g < 0) ? (-1 - g) : g;
                g = (g >= M2) ? (2 * M2 - 1 - g) : g;
                float v = (g & 1) ? s2o[g >> 1] : s2e[g >> 1];
                sa = fmaf(v, c_dlo[j], sa);
                sd = fmaf(v, c_dhi[j], sd);
            }
        }
        if (k & 1) a3o[k >> 1] = sa; else a3e[k >> 1] = sa;
        d3r[k] = sd;
    }
    __syncthreads();
    float* a4r = a4 + (size_t)row * M4P;
    float* d4r = d4 + (size_t)row * M4P;
    for (int k = tid; k < M4; k += 256) {
        float sa, sd;
        if (k >= 3 && k <= 514) {
            u64 acc = 0ull;
#pragma unroll
            for (int s = 0; s < 4; s++) {
                float vo = a3o[k - s], ve = a3e[k - s];
                acc = ffma2(pk2(vo, vo), lh[2 * s], acc);
                acc = ffma2(pk2(ve, ve), lh[2 * s + 1], acc);
            }
            float2 ad = up2(acc);
            sa = ad.x; sd = ad.y;
        } else {
            sa = 0.f; sd = 0.f;
#pragma unroll
            for (int j = 0; j < 8; j++) {
                int g = 2 * k + 1 - j;
                g = (g < 0) ? (-1 - g) : g;
                g = (g >= M3) ? (2 * M3 - 1 - g) : g;
                float v = (g & 1) ? a3o[g >> 1] : a3e[g >> 1];
                sa = fmaf(v, c_dlo[j], sa);
                sd = fmaf(v, c_dhi[j], sd);
            }
        }
        a4r[k] = sa;
        d4r[k] = sd;
    }
}

// ---------------------------------------------------------------------------
// Forward transposes (z=0: a4->a4t, 1: d4->d4t, 2: w1->wt1, 3: w2->wt2)
// ---------------------------------------------------------------------------
__global__ void tr4_kernel(const float* __restrict__ s0, const float* __restrict__ s1,
                           const float* __restrict__ s2, const float* __restrict__ s3,
                           float* __restrict__ o0, float* __restrict__ o1,
                           float* __restrict__ o2, float* __restrict__ o3) {
    __shared__ float tile[32][33];
    int z = blockIdx.z;
    const float* __restrict__ src; float* __restrict__ dst; int R, ss, ds;
    if (z == 0)      { src = s0; dst = o0; R = R_TOT; ss = M4P; ds = R_TOT; }
    else if (z == 1) { src = s1; dst = o1; R = R_TOT; ss = M4P; ds = R_TOT; }
    else if (z == 2) { src = s2; dst = o2; R = 4096;  ss = M4;  ds = 4096; }
    else             { src = s3; dst = o3; R = 4096;  ss = M4;  ds = 4096; }
    int c0 = blockIdx.x * 32;
    int r0 = blockIdx.y * 32;
    if (r0 >= R) return;
    int tx = threadIdx.x, ty = threadIdx.y;
#pragma unroll
    for (int i = 0; i < 32; i += 8) {
        int r = r0 + ty + i, c = c0 + tx;
        if (r < R && c < M4) tile[ty + i][tx] = src[(size_t)r * ss + c];
    }
    __syncthreads();
#pragma unroll
    for (int i = 0; i < 32; i += 8) {
        int c = c0 + ty + i, r = r0 + tx;
        if (c < M4 && r < R) dst[(size_t)c * ds + r] = tile[tx][ty + i];
    }
}

// ---------------------------------------------------------------------------
// Back transposes (z=0: a4mt->a4m, 1: d4mt->d4m)
// ---------------------------------------------------------------------------
__global__ void tr2_kernel(const float* __restrict__ s0, const float* __restrict__ s1,
                           float* __restrict__ o0, float* __restrict__ o1) {
    __shared__ float tile[32][33];
    const float* __restrict__ src = blockIdx.z ? s1 : s0;
    float* __restrict__ dst = blockIdx.z ? o1 : o0;
    int c0 = blockIdx.x * 32;
    int r0 = blockIdx.y * 32;
    int tx = threadIdx.x, ty = threadIdx.y;
#pragma unroll
    for (int i = 0; i < 32; i += 8) {
        int r = r0 + ty + i;
        if (r < M4) tile[ty + i][tx] = src[(size_t)r * R_TOT + c0 + tx];
    }
    __syncthreads();
#pragma unroll
    for (int i = 0; i < 32; i += 8) {
        int r = r0 + tx;
        if (r < M4) dst[(size_t)(c0 + ty + i) * M4P + r] = tile[tx][ty + i];
    }
}

// ---------------------------------------------------------------------------
// Channel mix: 2 batches per thread share each w load; f32x2 accumulate. (R12 WIN)
// ---------------------------------------------------------------------------
__global__ __launch_bounds__(256) void mix_kernel(
    const float* __restrict__ a4t, const float* __restrict__ d4t,
    const float* __restrict__ wt1, const float* __restrict__ wt2,
    float* __restrict__ a4mt, float* __restrict__ d4mt) {
    int k = blockIdx.x;
    const float* __restrict__ in = blockIdx.y ? d4t : a4t;
    const float* __restrict__ wt = blockIdx.y ? wt2 : wt1;
    float* __restrict__ out = blockIdx.y ? d4mt : a4mt;

    __shared__ __align__(16) float ws[4096];
    __shared__ float as[32 * 65];
    int tid = threadIdx.x;
    const float4* __restrict__ wk4 = reinterpret_cast<const float4*>(wt + (size_t)k * 4096);
    const float4* __restrict__ ik4 = reinterpret_cast<const float4*>(in + (size_t)k * R_TOT);
    float4* ws4w = reinterpret_cast<float4*>(ws);
    for (int idx = tid; idx < 1024; idx += 256) ws4w[idx] = __ldg(&wk4[idx]);
    for (int idx = tid; idx < 512; idx += 256) {
        float4 v = __ldg(&ik4[idx]);
        int b = idx >> 4, i = (idx & 15) * 4;
        float* p = &as[b * 65 + i];
        p[0] = v.x; p[1] = v.y; p[2] = v.z; p[3] = v.w;
    }
    __syncthreads();

    int b2 = tid >> 4;   // 0..15
    int lg = tid & 15;   // 0..15
    const ulonglong2* wsu = reinterpret_cast<const ulonglong2*>(ws);
    u64 a0a = 0ull, a0b = 0ull, a1a = 0ull, a1b = 0ull;
#pragma unroll
    for (int i = 0; i < 64; i++) {
        float v0 = as[b2 * 65 + i];
        float v1 = as[(b2 + 16) * 65 + i];
        ulonglong2 w = wsu[i * 16 + lg];
        u64 p0 = pk2(v0, v0), p1 = pk2(v1, v1);
        a0a = ffma2(p0, w.x, a0a); a0b = ffma2(p0, w.y, a0b);
        a1a = ffma2(p1, w.x, a1a); a1b = ffma2(p1, w.y, a1b);
    }
    float2 e0 = up2(a0a), e1 = up2(a0b), e2 = up2(a1a), e3 = up2(a1b);
    float* ob = out + (size_t)k * R_TOT;
    *reinterpret_cast<float4*>(ob + b2 * 64 + lg * 4)        = make_float4(e0.x, e0.y, e1.x, e1.y);
    *reinterpret_cast<float4*>(ob + (b2 + 16) * 64 + lg * 4) = make_float4(e2.x, e2.y, e3.x, e3.y);
}

// ---------------------------------------------------------------------------
// K6: fused IDWT L4->3 + L3->2 per row (pair outputs via f32x2).
// ---------------------------------------------------------------------------
__global__ __launch_bounds__(256) void idwt432_kernel(const float* __restrict__ a4m,
                                                      const float* __restrict__ d4m,
                                                      const float* __restrict__ d3,
                                                      float* __restrict__ a2r) {
    __shared__ __align__(16) float sa4[520];
    __shared__ __align__(16) float sd4[520];
    __shared__ __align__(16) float sa3[1032];
    __shared__ __align__(16) float sd3[1032];
    int row = blockIdx.x, tid = threadIdx.x;
    const u64* lh = reinterpret_cast<const u64*>(c_lh);
    const float4* pa = reinterpret_cast<const float4*>(a4m + (size_t)row * M4P);
    const float4* pd = reinterpret_cast<const float4*>(d4m + (size_t)row * M4P);
    for (int i = tid; i < 130; i += 256) {
        *reinterpret_cast<float4*>(&sa4[4 * i]) = __ldg(&pa[i]);
        *reinterpret_cast<float4*>(&sd4[4 * i]) = __ldg(&pd[i]);
    }
    const float4* p3 = reinterpret_cast<const float4*>(d3 + (size_t)row * M3P);
    for (int i = tid; i < 258; i += 256)
        *reinterpret_cast<float4*>(&sd3[4 * i]) = __ldg(&p3[i]);
    __syncthreads();

    for (int q = tid; q < (M3 + 1) / 2; q += 256) {
        u64 accE = 0ull, accO = 0ull;
#pragma unroll
        for (int t = 0; t < 4; t++) {
            u64 ad = pk2(sa4[q + t], sd4[q + t]);
            accE = ffma2(ad, lh[2 * t + 1], accE);
            accO = ffma2(ad, lh[2 * t], accO);
        }
        float2 e = up2(accE), o = up2(accO);
        sa3[2 * q] = e.x + e.y;
        if (2 * q + 1 < M3) sa3[2 * q + 1] = o.x + o.y;
    }
    __syncthreads();

    float* outr = a2r + (size_t)row * M2P;
    for (int q = tid; q < (M2 + 1) / 2; q += 256) {
        u64 accE = 0ull, accO = 0ull;
#pragma unroll
        for (int t = 0; t < 4; t++) {
            u64 ad = pk2(sa3[q + t], sd3[q + t]);
            accE = ffma2(ad, lh[2 * t + 1], accE);
            accO = ffma2(ad, lh[2 * t], accO);
        }
        float2 e = up2(accE), o = up2(accO);
        outr[2 * q] = e.x + e.y;
        if (2 * q + 1 < M2) outr[2 * q + 1] = o.x + o.y;
    }
}

// ---------------------------------------------------------------------------
// K7: fused IDWT L2->1 + L1->0 + transpose-back + dense (f32x2) + mish.
// R11 conflict-free dense tiling; dk read via __ldg (L1-resident, 16 KB);
// SMEM 63.2 KB -> 3 blocks/SM. Fast mish via exp identity.
// ---------------------------------------------------------------------------
__device__ __forceinline__ float mish_f(float v) {
    // mish(v) = v * tanh(softplus(v)); tanh(log(1+e)) = ((1+e)^2-1)/((1+e)^2+1)
    float e = __expf(v);
    float t = 1.f + e;
    float t2 = fmaf(t, t, 1.f);            // (1+e)^2 + 1
    float n  = fmaf(t, t, -1.f);           // (1+e)^2 - 1
    float r = v * __fdividef(n, t2);
    return (v > 20.f) ? v : r;
}

__global__ __launch_bounds__(256) void ifinal2_kernel(
    const float* __restrict__ a2r, const float* __restrict__ d2,
    const float* __restrict__ d1, const float* __restrict__ x,
    const float* __restrict__ dk, const float* __restrict__ bias,
    float* __restrict__ out) {
    extern __shared__ float sm[];
    float* xs  = sm;            // 64*65 = 4160
    float* ys  = xs + 4160;     // 4160
    float* sA  = ys + 4160;     // 64*36 = 2304 (a1 recon window, 35 used)
    float* sD  = sA + 2304;     // 2304          (d1 window, 35 used)
    float* sA2 = sD + 2304;     // 64*22 = 1408 (21 used)
    float* sD2 = sA2 + 1408;    // 1408
    float* bs  = sD2 + 1408;    // 64
    // total 15808 floats = 63232 B -> 3 blocks/SM

    int b = blockIdx.y;
    int n0 = blockIdx.x * 64;
    int r0 = n0 >> 1;   // even
    int q0 = r0 >> 1;
    int tid = threadIdx.x;
    const u64* lh = reinterpret_cast<const u64*>(c_lh);

    if (tid < 64) bs[tid] = __ldg(&bias[tid]);
    for (int idx = tid; idx < 64 * 21; idx += 256) {
        int c = idx / 21, i = idx - c * 21;
        size_t off = (size_t)(b * 64 + c) * M2P + q0 + i;
        sA2[c * 22 + i] = __ldg(&a2r[off]);
        sD2[c * 22 + i] = __ldg(&d2[off]);
    }
    for (int idx = tid; idx < 64 * 35; idx += 256) {
        int c = idx / 35, i = idx - c * 35;
        sD[c * 36 + i] = __ldg(&d1[(size_t)(b * 64 + c) * M1P + r0 + i]);
    }
    {   // x tile via float4: 64 nn x 16 groups
        const float4* xg = reinterpret_cast<const float4*>(x);
        for (int idx = tid; idx < 64 * 16; idx += 256) {
            int nn = idx >> 4, ig = idx & 15;
            float4 v = __ldg(&xg[((size_t)b * N0 + n0 + nn) * 16 + ig]);
            float* p = &xs[nn * 65 + ig * 4];
            p[0] = v.x; p[1] = v.y; p[2] = v.z; p[3] = v.w;
        }
    }
    __syncthreads();

    // reconstruct a1 window: pairs rr = 2m, 2m+1 (m = 0..17)
    for (int idx = tid; idx < 64 * 18; idx += 256) {
        int c = idx / 18, m = idx - c * 18;
        const float* A = &sA2[c * 22 + m];
        const float* D = &sD2[c * 22 + m];
        u64 accE = 0ull, accO = 0ull;
#pragma unroll
        for (int t = 0; t < 4; t++) {
            u64 ad = pk2(A[t], D[t]);
            accE = ffma2(ad, lh[2 * t + 1], accE);
            accO = ffma2(ad, lh[2 * t], accO);
        }
        float2 e = up2(accE), o = up2(accO);
        sA[c * 36 + 2 * m] = e.x + e.y;
        sA[c * 36 + 2 * m + 1] = o.x + o.y;
    }
    __syncthreads();

    // IDWT level 1 into ys[nn][c]: pairs nn = 2m, 2m+1 (m = 0..31)
    for (int idx = tid; idx < 64 * 32; idx += 256) {
        int c = idx >> 5, m = idx & 31;
        const float* A = &sA[c * 36 + m];
        const float* D = &sD[c * 36 + m];
        u64 accE = 0ull, accO = 0ull;
#pragma unroll
        for (int t = 0; t < 4; t++) {
            u64 ad = pk2(A[t], D[t]);
            accE = ffma2(ad, lh[2 * t + 1], accE);
            accO = ffma2(ad, lh[2 * t], accO);
        }
        float2 e = up2(accE), o = up2(accO);
        ys[(2 * m) * 65 + c] = e.x + e.y;
        ys[(2 * m + 1) * 65 + c] = o.x + o.y;
    }
    __syncthreads();

    // dense shortcut (f32x2) + add + mish; thread: 2 nn (nn, nn+32) x 8 c
    // dk read from gmem (L1-resident) with conflict-free 128B/warp pattern.
    int nn = tid >> 3;
    int lg = tid & 7;
    int g = lg * 4;
    const ulonglong2* dk2 = reinterpret_cast<const ulonglong2*>(dk);
    u64 bi0 = pk2(bs[g], bs[g + 1]);
    u64 bi1 = pk2(bs[g + 2], bs[g + 3]);
    u64 bi2 = pk2(bs[g + 32], bs[g + 33]);
    u64 bi3 = pk2(bs[g + 34], bs[g + 35]);
    u64 a00 = bi0, a01 = bi1, a02 = bi2, a03 = bi3;
    u64 a10 = bi0, a11 = bi1, a12 = bi2, a13 = bi3;
#pragma unroll
    for (int i = 0; i < 64; i++) {
        float xv0 = xs[nn * 65 + i];
        float xv1 = xs[(nn + 32) * 65 + i];
        u64 p0 = pk2(xv0, xv0), p1 = pk2(xv1, xv1);
        ulonglong2 w0 = __ldg(&dk2[i * 16 + lg]);
        ulonglong2 w1 = __ldg(&dk2[i * 16 + 8 + lg]);
        a00 = ffma2(p0, w0.x, a00); a01 = ffma2(p0, w0.y, a01);
        a02 = ffma2(p0, w1.x, a02); a03 = ffma2(p0, w1.y, a03);
        a10 = ffma2(p1, w0.x, a10); a11 = ffma2(p1, w0.y, a11);
        a12 = ffma2(p1, w1.x, a12); a13 = ffma2(p1, w1.y, a13);
    }
#pragma unroll
    for (int h = 0; h < 2; h++) {
        int row = nn + h * 32;
        float2 q0_ = up2(h ? a10 : a00), q1_ = up2(h ? a11 : a01);
        float2 q2_ = up2(h ? a12 : a02), q3_ = up2(h ? a13 : a03);
        float v0[4] = {q0_.x, q0_.y, q1_.x, q1_.y};
        float v1[4] = {q2_.x, q2_.y, q3_.x, q3_.y};
#pragma unroll
        for (int u = 0; u < 4; u++) {
            v0[u] = mish_f(v0[u] + ys[row * 65 + g + u]);
            v1[u] = mish_f(v1[u] + ys[row * 65 + g + 32 + u]);
        }
        float4* op = reinterpret_cast<float4*>(&out[((size_t)b * N0 + n0 + row) * CB]);
        op[lg] = make_float4(v0[0], v0[1], v0[2], v0[3]);
        op[8 + lg] = make_float4(v1[0], v1[1], v1[2], v1[3]);
    }
}

// ---------------------------------------------------------------------------
extern "C" void kernel_launch(void* const* d_in, const int* in_sizes, int n_in,
                              void* d_out, int out_size) {
    (void)in_sizes; (void)n_in; (void)out_size;
    const float* x    = (const float*)d_in[0];
    const float* w1   = (const float*)d_in[1];
    const float* w2   = (const float*)d_in[2];
    const float* dk   = (const float*)d_in[3];
    const float* bias = (const float*)d_in[4];
    float* out = (float*)d_out;

    float *d1, *a2, *d2, *d3, *a4, *d4;
    float *a4t, *d4t, *a4mt, *d4mt, *a4m, *d4m, *wt1, *wt2;
    cudaGetSymbolAddress((void**)&d1,   g_d1);
    cudaGetSymbolAddress((void**)&a2,   g_a2);
    cudaGetSymbolAddress((void**)&d2,   g_d2);
    cudaGetSymbolAddress((void**)&d3,   g_d3);
    cudaGetSymbolAddress((void**)&a4,   g_a4);
    cudaGetSymbolAddress((void**)&d4,   g_d4);
    cudaGetSymbolAddress((void**)&a4t,  g_a4t);
    cudaGetSymbolAddress((void**)&d4t,  g_d4t);
    cudaGetSymbolAddress((void**)&a4mt, g_a4mt);
    cudaGetSymbolAddress((void**)&d4mt, g_d4mt);
    cudaGetSymbolAddress((void**)&a4m,  g_a4m);
    cudaGetSymbolAddress((void**)&d4m,  g_d4m);
    cudaGetSymbolAddress((void**)&wt1,  g_wt1);
    cudaGetSymbolAddress((void**)&wt2,  g_wt2);

    const int K1_SMEM = (2 * 32 * 139 + 2 * 32 * 68) * (int)sizeof(float);  // 52992 B
    const int K7_SMEM = (4160 + 4160 + 2304 + 2304 + 1408 + 1408 + 64) * (int)sizeof(float); // 63232 B
    cudaFuncSetAttribute(dwt12_kernel, cudaFuncAttributeMaxDynamicSharedMemorySize, K1_SMEM);
    cudaFuncSetAttribute(ifinal2_kernel, cudaFuncAttributeMaxDynamicSharedMemorySize, K7_SMEM);

    dim3 trb(32, 8);
    // 1. fused transpose + DWT L1 + L2
    dwt12_kernel<<<dim3(33, 64), 256, K1_SMEM>>>(x, d1, a2, d2);
    // 2. fused DWT L3 + L4
    dwt34_kernel<<<R_TOT, 256>>>(a2, d3, a4, d4);
    // 3. forward transposes
    tr4_kernel<<<dim3((M4 + 31) / 32, 4096 / 32, 4), trb>>>(a4, d4, w1, w2, a4t, d4t, wt1, wt2);
    // 4. channel mix
    mix_kernel<<<dim3(M4, 2), 256>>>(a4t, d4t, wt1, wt2, a4mt, d4mt);
    // 5. transpose mixed back
    tr2_kernel<<<dim3(R_TOT / 32, (M4 + 31) / 32, 2), trb>>>(a4mt, d4mt, a4m, d4m);
    // 6. fused IDWT L4->3->2
    idwt432_kernel<<<R_TOT, 256>>>(a4m, d4m, d3, a2);
    // 7. fused IDWT L2->1 + L1->0 + dense + fast mish (3 blocks/SM)
    ifinal2_kernel<<<dim3(N0 / 64, BB), 256, K7_SMEM>>>(a2, d2, d1, x, dk, bias, out);
}

// round 16
// speedup vs baseline: 1.2164x; 1.0732x over previous
#include <cuda_runtime.h>
#include <math.h>

#define R_TOT 2048   // B*C rows
#define N0 8192
#define M1 4099
#define M2 2053
#define M3 1030
#define M4 518
#define M1P 4100
#define M2P 2056
#define M3P 1032
#define M4P 520
#define CB 64
#define BB 32

__constant__ float c_dlo[8] = {-0.010597401784997278f, 0.032883011666982945f, 0.030841381835986965f,
                               -0.18703481171888114f, -0.02798376941698385f, 0.6308807679295904f,
                               0.7148465705525415f, 0.23037781330885523f};
__constant__ float c_dhi[8] = {-0.23037781330885523f, 0.7148465705525415f, -0.6308807679295904f,
                               -0.02798376941698385f, 0.18703481171888114f, 0.030841381835986965f,
                               -0.032883011666982945f, -0.010597401784997278f};
// packed (dlo[j], dhi[j]) pairs for f32x2 math
__constant__ float2 c_lh[8] = {
    {-0.010597401784997278f, -0.23037781330885523f},
    {0.032883011666982945f,  0.7148465705525415f},
    {0.030841381835986965f,  -0.6308807679295904f},
    {-0.18703481171888114f,  -0.02798376941698385f},
    {-0.02798376941698385f,  0.18703481171888114f},
    {0.6308807679295904f,    0.030841381835986965f},
    {0.7148465705525415f,    -0.032883011666982945f},
    {0.23037781330885523f,   -0.010597401784997278f}};

typedef unsigned long long u64;
__device__ __forceinline__ u64 ffma2(u64 a, u64 b, u64 c) {
    u64 d;
    asm("fma.rn.f32x2 %0, %1, %2, %3;" : "=l"(d) : "l"(a), "l"(b), "l"(c));
    return d;
}
__device__ __forceinline__ u64 pk2(float x, float y) {
    u64 r;
    asm("mov.b64 %0, {%1, %2};" : "=l"(r) : "f"(x), "f"(y));
    return r;
}
__device__ __forceinline__ float2 up2(u64 v) {
    float2 r;
    asm("mov.b64 {%0, %1}, %2;" : "=f"(r.x), "=f"(r.y) : "l"(v));
    return r;
}

// Scratch (static device globals; allocation-free per harness rules)
__device__ __align__(256) float g_a2[(size_t)R_TOT * M2P];   // fwd a2, later a2-recon
__device__ __align__(256) float g_d2[(size_t)R_TOT * M2P];
__device__ __align__(256) float g_d3[(size_t)R_TOT * M3P];
__device__ __align__(256) float g_a4[(size_t)R_TOT * M4P];
__device__ __align__(256) float g_d4[(size_t)R_TOT * M4P];
__device__ __align__(256) float g_a4t[(size_t)M4 * R_TOT];   // [k][row]
__device__ __align__(256) float g_d4t[(size_t)M4 * R_TOT];
__device__ __align__(256) float g_a4mt[(size_t)M4 * R_TOT];
__device__ __align__(256) float g_d4mt[(size_t)M4 * R_TOT];
__device__ __align__(256) float g_a4m[(size_t)R_TOT * M4P];  // [row][k]
__device__ __align__(256) float g_d4m[(size_t)R_TOT * M4P];
__device__ __align__(256) float g_wt1[(size_t)M4 * CB * CB]; // [k][i*64+o]
__device__ __align__(256) float g_wt2[(size_t)M4 * CB * CB];

// ---------------------------------------------------------------------------
// K1: fused transpose + DWT L1 + L2 (halo recompute). a1 only in SMEM.
// d1 no longer stored (recomputed in ifinal2), so a1 body is lo-filter only.
// ---------------------------------------------------------------------------
__device__ __forceinline__ void dwt12_a1_body(
    int cc, int kk, int K0,
    const float* __restrict__ xe, const float* __restrict__ xo,
    float* __restrict__ ae, float* __restrict__ ao) {
    int k1 = 2 * K0 - 6 + kk;
    if (k1 < 0 || k1 >= M1) return;
    const float* pe = &xe[cc * 139 + kk + 3];
    const float* po = &xo[cc * 139 + kk + 3];
    float s = 0.f;
#pragma unroll
    for (int t = 0; t < 4; t++)
        s = fmaf(po[-t], c_dlo[2 * t], fmaf(pe[-t], c_dlo[2 * t + 1], s));
    int tl = (k1 >> 1) - (K0 - 3);
    if (k1 & 1) ao[cc * 68 + tl] = s;
    else        ae[cc * 68 + tl] = s;
}

__global__ __launch_bounds__(256) void dwt12_kernel(const float* __restrict__ x,
                                                    float* __restrict__ a2,
                                                    float* __restrict__ d2) {
    extern __shared__ float sm[];
    float* xe = sm;                 // [32][139]
    float* xo = sm + 32 * 139;      // [32][139]
    float* ae = sm + 2 * 32 * 139;  // [32][68]
    float* ao = ae + 32 * 68;       // [32][68]
    int K0 = blockIdx.x * 64;
    int ct = blockIdx.y;
    int b = ct >> 1, c0 = (ct & 1) * 32;
    int tid = threadIdx.x;
    int xbase = 4 * K0 - 18;        // even
    const u64* lh = reinterpret_cast<const u64*>(c_lh);

    // x window via float4 over channels: 276 rows x 8 cgroups
    for (int idx = tid; idx < 276 * 8; idx += 256) {
        int nn = idx >> 3, cg = idx & 7;
        int q = xbase + nn;
        q = (q < 0) ? (-1 - q) : q;
        q = (q >= N0) ? (2 * N0 - 1 - q) : q;
        float4 v = __ldg(reinterpret_cast<const float4*>(&x[((size_t)b * N0 + q) * CB + c0 + cg * 4]));
        int u = nn >> 1;
        float* dst = (nn & 1) ? xo : xe;
        int cb4 = cg * 4;
        dst[(cb4 + 0) * 139 + u] = v.x;
        dst[(cb4 + 1) * 139 + u] = v.y;
        dst[(cb4 + 2) * 139 + u] = v.z;
        dst[(cb4 + 3) * 139 + u] = v.w;
    }
    __syncthreads();

    // a1 window [2K0-6, 2K0+127] (kk 0..133): pow2 main loop + tail
    for (int idx = tid; idx < 32 * 128; idx += 256) {
        dwt12_a1_body(idx >> 7, idx & 127, K0, xe, xo, ae, ao);
    }
    {   // tail kk 128..133
        int cc = tid >> 3, kk = 128 + (tid & 7);
        if (kk < 134) dwt12_a1_body(cc, kk, K0, xe, xo, ae, ao);
    }
    __syncthreads();

    // level 2
    for (int idx = tid; idx < 32 * 64; idx += 256) {
        int cc = idx >> 6, kk2 = idx & 63;
        int k2 = K0 + kk2;
        if (k2 >= M2) continue;
        float sa, sd;
        if (k2 >= 3 && k2 <= 2048) {
            const float* pe = &ae[cc * 68 + kk2 + 3];
            const float* po = &ao[cc * 68 + kk2 + 3];
            u64 acc = 0ull;
#pragma unroll
            for (int s = 0; s < 4; s++) {
                float vo = po[-s], ve = pe[-s];
                acc = ffma2(pk2(vo, vo), lh[2 * s], acc);
                acc = ffma2(pk2(ve, ve), lh[2 * s + 1], acc);
            }
            float2 ad = up2(acc);
            sa = ad.x; sd = ad.y;
        } else {
            sa = 0.f; sd = 0.f;
#pragma unroll
            for (int j = 0; j < 8; j++) {
                int g = 2 * k2 + 1 - j;
                g = (g < 0) ? (-1 - g) : g;
                g = (g >= M1) ? (2 * M1 - 1 - g) : g;
                int tl = (g >> 1) - (K0 - 3);
                float v = (g & 1) ? ao[cc * 68 + tl] : ae[cc * 68 + tl];
                sa = fmaf(v, c_dlo[j], sa);
                sd = fmaf(v, c_dhi[j], sd);
            }
        }
        size_t off = (size_t)(b * 64 + c0 + cc) * M2P + k2;
        a2[off] = sa;
        d2[off] = sd;
    }
}

// ---------------------------------------------------------------------------
// K2: fused DWT L3 + L4 per row. a3 only in SMEM.
// ---------------------------------------------------------------------------
__global__ __launch_bounds__(256) void dwt34_kernel(const float* __restrict__ a2,
                                                    float* __restrict__ d3,
                                                    float* __restrict__ a4,
                                                    float* __restrict__ d4) {
    __shared__ __align__(16) float s2e[1032];
    __shared__ __align__(16) float s2o[1032];
    __shared__ __align__(16) float a3e[520];
    __shared__ __align__(16) float a3o[520];
    int row = blockIdx.x, tid = threadIdx.x;
    const u64* lh = reinterpret_cast<const u64*>(c_lh);
    const float4* s4 = reinterpret_cast<const float4*>(a2 + (size_t)row * M2P);
    for (int i = tid; i < 514; i += 256) {
        float4 v = __ldg(&s4[i]);
        int u = 2 * i;
        s2e[u] = v.x; s2o[u] = v.y; s2e[u + 1] = v.z; s2o[u + 1] = v.w;
    }
    __syncthreads();
    float* d3r = d3 + (size_t)row * M3P;
    for (int k = tid; k < M3; k += 256) {
        float sa, sd;
        if (k >= 3 && k <= 1025) {
            u64 acc = 0ull;
#pragma unroll
            for (int s = 0; s < 4; s++) {
                float vo = s2o[k - s], ve = s2e[k - s];
                acc = ffma2(pk2(vo, vo), lh[2 * s], acc);
                acc = ffma2(pk2(ve, ve), lh[2 * s + 1], acc);
            }
            float2 ad = up2(acc);
            sa = ad.x; sd = ad.y;
        } else {
            sa = 0.f; sd = 0.f;
#pragma unroll
            for (int j = 0; j < 8; j++) {
                int g = 2 * k + 1 - j;
                g = (g < 0) ? (-1 - g) : g;
                g = (g >= M2) ? (2 * M2 - 1 - g) : g;
                float v = (g & 1) ? s2o[g >> 1] : s2e[g >> 1];
                sa = fmaf(v, c_dlo[j], sa);
                sd = fmaf(v, c_dhi[j], sd);
            }
        }
        if (k & 1) a3o[k >> 1] = sa; else a3e[k >> 1] = sa;
        d3r[k] = sd;
    }
    __syncthreads();
    float* a4r = a4 + (size_t)row * M4P;
    float* d4r = d4 + (size_t)row * M4P;
    for (int k = tid; k < M4; k += 256) {
        float sa, sd;
        if (k >= 3 && k <= 514) {
            u64 acc = 0ull;
#pragma unroll
            for (int s = 0; s < 4; s++) {
                float vo = a3o[k - s], ve = a3e[k - s];
                acc = ffma2(pk2(vo, vo), lh[2 * s], acc);
                acc = ffma2(pk2(ve, ve), lh[2 * s + 1], acc);
            }
            float2 ad = up2(acc);
            sa = ad.x; sd = ad.y;
        } else {
            sa = 0.f; sd = 0.f;
#pragma unroll
            for (int j = 0; j < 8; j++) {
                int g = 2 * k + 1 - j;
                g = (g < 0) ? (-1 - g) : g;
                g = (g >= M3) ? (2 * M3 - 1 - g) : g;
                float v = (g & 1) ? a3o[g >> 1] : a3e[g >> 1];
                sa = fmaf(v, c_dlo[j], sa);
                sd = fmaf(v, c_dhi[j], sd);
            }
        }
        a4r[k] = sa;
        d4r[k] = sd;
    }
}

// ---------------------------------------------------------------------------
// Forward transposes (z=0: a4->a4t, 1: d4->d4t, 2: w1->wt1, 3: w2->wt2)
// ---------------------------------------------------------------------------
__global__ void tr4_kernel(const float* __restrict__ s0, const float* __restrict__ s1,
                           const float* __restrict__ s2, const float* __restrict__ s3,
                           float* __restrict__ o0, float* __restrict__ o1,
                           float* __restrict__ o2, float* __restrict__ o3) {
    __shared__ float tile[32][33];
    int z = blockIdx.z;
    const float* __restrict__ src; float* __restrict__ dst; int R, ss, ds;
    if (z == 0)      { src = s0; dst = o0; R = R_TOT; ss = M4P; ds = R_TOT; }
    else if (z == 1) { src = s1; dst = o1; R = R_TOT; ss = M4P; ds = R_TOT; }
    else if (z == 2) { src = s2; dst = o2; R = 4096;  ss = M4;  ds = 4096; }
    else             { src = s3; dst = o3; R = 4096;  ss = M4;  ds = 4096; }
    int c0 = blockIdx.x * 32;
    int r0 = blockIdx.y * 32;
    if (r0 >= R) return;
    int tx = threadIdx.x, ty = threadIdx.y;
#pragma unroll
    for (int i = 0; i < 32; i += 8) {
        int r = r0 + ty + i, c = c0 + tx;
        if (r < R && c < M4) tile[ty + i][tx] = src[(size_t)r * ss + c];
    }
    __syncthreads();
#pragma unroll
    for (int i = 0; i < 32; i += 8) {
        int c = c0 + ty + i, r = r0 + tx;
        if (c < M4 && r < R) dst[(size_t)c * ds + r] = tile[tx][ty + i];
    }
}

// ---------------------------------------------------------------------------
// Back transposes (z=0: a4mt->a4m, 1: d4mt->d4m)
// ---------------------------------------------------------------------------
__global__ void tr2_kernel(const float* __restrict__ s0, const float* __restrict__ s1,
                           float* __restrict__ o0, float* __restrict__ o1) {
    __shared__ float tile[32][33];
    const float* __restrict__ src = blockIdx.z ? s1 : s0;
    float* __restrict__ dst = blockIdx.z ? o1 : o0;
    int c0 = blockIdx.x * 32;
    int r0 = blockIdx.y * 32;
    int tx = threadIdx.x, ty = threadIdx.y;
#pragma unroll
    for (int i = 0; i < 32; i += 8) {
        int r = r0 + ty + i;
        if (r < M4) tile[ty + i][tx] = src[(size_t)r * R_TOT + c0 + tx];
    }
    __syncthreads();
#pragma unroll
    for (int i = 0; i < 32; i += 8) {
        int r = r0 + tx;
        if (r < M4) dst[(size_t)(c0 + ty + i) * M4P + r] = tile[tx][ty + i];
    }
}

// ---------------------------------------------------------------------------
// Channel mix: 2 batches per thread share each w load; f32x2 accumulate. (R12 WIN)
// ---------------------------------------------------------------------------
__global__ __launch_bounds__(256) void mix_kernel(
    const float* __restrict__ a4t, const float* __restrict__ d4t,
    const float* __restrict__ wt1, const float* __restrict__ wt2,
    float* __restrict__ a4mt, float* __restrict__ d4mt) {
    int k = blockIdx.x;
    const float* __restrict__ in = blockIdx.y ? d4t : a4t;
    const float* __restrict__ wt = blockIdx.y ? wt2 : wt1;
    float* __restrict__ out = blockIdx.y ? d4mt : a4mt;

    __shared__ __align__(16) float ws[4096];
    __shared__ float as[32 * 65];
    int tid = threadIdx.x;
    const float4* __restrict__ wk4 = reinterpret_cast<const float4*>(wt + (size_t)k * 4096);
    const float4* __restrict__ ik4 = reinterpret_cast<const float4*>(in + (size_t)k * R_TOT);
    float4* ws4w = reinterpret_cast<float4*>(ws);
    for (int idx = tid; idx < 1024; idx += 256) ws4w[idx] = __ldg(&wk4[idx]);
    for (int idx = tid; idx < 512; idx += 256) {
        float4 v = __ldg(&ik4[idx]);
        int b = idx >> 4, i = (idx & 15) * 4;
        float* p = &as[b * 65 + i];
        p[0] = v.x; p[1] = v.y; p[2] = v.z; p[3] = v.w;
    }
    __syncthreads();

    int b2 = tid >> 4;   // 0..15
    int lg = tid & 15;   // 0..15
    const ulonglong2* wsu = reinterpret_cast<const ulonglong2*>(ws);
    u64 a0a = 0ull, a0b = 0ull, a1a = 0ull, a1b = 0ull;
#pragma unroll
    for (int i = 0; i < 64; i++) {
        float v0 = as[b2 * 65 + i];
        float v1 = as[(b2 + 16) * 65 + i];
        ulonglong2 w = wsu[i * 16 + lg];
        u64 p0 = pk2(v0, v0), p1 = pk2(v1, v1);
        a0a = ffma2(p0, w.x, a0a); a0b = ffma2(p0, w.y, a0b);
        a1a = ffma2(p1, w.x, a1a); a1b = ffma2(p1, w.y, a1b);
    }
    float2 e0 = up2(a0a), e1 = up2(a0b), e2 = up2(a1a), e3 = up2(a1b);
    float* ob = out + (size_t)k * R_TOT;
    *reinterpret_cast<float4*>(ob + b2 * 64 + lg * 4)        = make_float4(e0.x, e0.y, e1.x, e1.y);
    *reinterpret_cast<float4*>(ob + (b2 + 16) * 64 + lg * 4) = make_float4(e2.x, e2.y, e3.x, e3.y);
}

// ---------------------------------------------------------------------------
// K6: fused IDWT L4->3 + L3->2 per row (pair outputs via f32x2).
// ---------------------------------------------------------------------------
__global__ __launch_bounds__(256) void idwt432_kernel(const float* __restrict__ a4m,
                                                      const float* __restrict__ d4m,
                                                      const float* __restrict__ d3,
                                                      float* __restrict__ a2r) {
    __shared__ __align__(16) float sa4[520];
    __shared__ __align__(16) float sd4[520];
    __shared__ __align__(16) float sa3[1032];
    __shared__ __align__(16) float sd3[1032];
    int row = blockIdx.x, tid = threadIdx.x;
    const u64* lh = reinterpret_cast<const u64*>(c_lh);
    const float4* pa = reinterpret_cast<const float4*>(a4m + (size_t)row * M4P);
    const float4* pd = reinterpret_cast<const float4*>(d4m + (size_t)row * M4P);
    for (int i = tid; i < 130; i += 256) {
        *reinterpret_cast<float4*>(&sa4[4 * i]) = __ldg(&pa[i]);
        *reinterpret_cast<float4*>(&sd4[4 * i]) = __ldg(&pd[i]);
    }
    const float4* p3 = reinterpret_cast<const float4*>(d3 + (size_t)row * M3P);
    for (int i = tid; i < 258; i += 256)
        *reinterpret_cast<float4*>(&sd3[4 * i]) = __ldg(&p3[i]);
    __syncthreads();

    for (int q = tid; q < (M3 + 1) / 2; q += 256) {
        u64 accE = 0ull, accO = 0ull;
#pragma unroll
        for (int t = 0; t < 4; t++) {
            u64 ad = pk2(sa4[q + t], sd4[q + t]);
            accE = ffma2(ad, lh[2 * t + 1], accE);
            accO = ffma2(ad, lh[2 * t], accO);
        }
        float2 e = up2(accE), o = up2(accO);
        sa3[2 * q] = e.x + e.y;
        if (2 * q + 1 < M3) sa3[2 * q + 1] = o.x + o.y;
    }
    __syncthreads();

    float* outr = a2r + (size_t)row * M2P;
    for (int q = tid; q < (M2 + 1) / 2; q += 256) {
        u64 accE = 0ull, accO = 0ull;
#pragma unroll
        for (int t = 0; t < 4; t++) {
            u64 ad = pk2(sa3[q + t], sd3[q + t]);
            accE = ffma2(ad, lh[2 * t + 1], accE);
            accO = ffma2(ad, lh[2 * t], accO);
        }
        float2 e = up2(accE), o = up2(accO);
        outr[2 * q] = e.x + e.y;
        if (2 * q + 1 < M2) outr[2 * q + 1] = o.x + o.y;
    }
}

// ---------------------------------------------------------------------------
// K7: fused IDWT L2->1 + L1->0 + transpose-back + dense (f32x2) + fast mish.
// d1 recomputed in-block from the (extended) x tile: kills the d1 gmem
// round-trip. x window rows [n0-6, n0+71] (78 rows) with reflect-at-load.
// ---------------------------------------------------------------------------
__device__ __forceinline__ float mish_f(float v) {
    float e = __expf(v);
    float t = 1.f + e;
    float t2 = fmaf(t, t, 1.f);
    float n  = fmaf(t, t, -1.f);
    float r = v * __fdividef(n, t2);
    return (v > 20.f) ? v : r;
}

__global__ __launch_bounds__(256) void ifinal2_kernel(
    const float* __restrict__ a2r, const float* __restrict__ d2,
    const float* __restrict__ x, const float* __restrict__ dk,
    const float* __restrict__ bias, float* __restrict__ out) {
    extern __shared__ float sm[];
    float* xs  = sm;            // 78*65 = 5070 (x window rows n0-6 .. n0+71)
    float* ys  = xs + 5070;     // 64*65 = 4160
    float* sA  = ys + 4160;     // 64*36 = 2304 (a1 recon window, 35 used)
    float* sD  = sA + 2304;     // 2304          (d1 window, 35 used, recomputed)
    float* sA2 = sD + 2304;     // 64*22 = 1408 (21 used)
    float* sD2 = sA2 + 1408;    // 1408
    float* bs  = sD2 + 1408;    // 64
    // total 16718 floats = 66872 B -> 3 blocks/SM

    int b = blockIdx.y;
    int n0 = blockIdx.x * 64;
    int r0 = n0 >> 1;   // even
    int q0 = r0 >> 1;
    int tid = threadIdx.x;
    const u64* lh = reinterpret_cast<const u64*>(c_lh);

    if (tid < 64) bs[tid] = __ldg(&bias[tid]);
    for (int idx = tid; idx < 64 * 21; idx += 256) {
        int c = idx / 21, i = idx - c * 21;
        size_t off = (size_t)(b * 64 + c) * M2P + q0 + i;
        sA2[c * 22 + i] = __ldg(&a2r[off]);
        sD2[c * 22 + i] = __ldg(&d2[off]);
    }
    {   // x window via float4: 78 rows x 16 groups, reflect-at-load
        const float4* xg = reinterpret_cast<const float4*>(x);
        for (int idx = tid; idx < 78 * 16; idx += 256) {
            int ln = idx >> 4, ig = idx & 15;
            int n = n0 - 6 + ln;
            n = (n < 0) ? (-1 - n) : n;
            n = (n >= N0) ? (2 * N0 - 1 - n) : n;
            float4 v = __ldg(&xg[((size_t)b * N0 + n) * 16 + ig]);
            float* p = &xs[ln * 65 + ig * 4];
            p[0] = v.x; p[1] = v.y; p[2] = v.z; p[3] = v.w;
        }
    }
    __syncthreads();

    // recompute d1 window: sD[c][rr] = sum_j dhi[j] * x_sym[2(r0+rr)+1-j]
    // local x row for tap = 2*rr + 7 - j; with t = 7-j: rows 2rr+t, filt dhi[7-t]
    for (int idx = tid; idx < 64 * 35; idx += 256) {
        int c = idx / 35, rr = idx - c * 35;
        const float* xp = &xs[(2 * rr) * 65 + c];
        float s = 0.f;
#pragma unroll
        for (int t = 0; t < 8; t++)
            s = fmaf(xp[t * 65], c_dhi[7 - t], s);
        sD[c * 36 + rr] = s;
    }

    // reconstruct a1 window: pairs rr = 2m, 2m+1 (m = 0..17)
    for (int idx = tid; idx < 64 * 18; idx += 256) {
        int c = idx / 18, m = idx - c * 18;
        const float* A = &sA2[c * 22 + m];
        const float* D = &sD2[c * 22 + m];
        u64 accE = 0ull, accO = 0ull;
#pragma unroll
        for (int t = 0; t < 4; t++) {
            u64 ad = pk2(A[t], D[t]);
            accE = ffma2(ad, lh[2 * t + 1], accE);
            accO = ffma2(ad, lh[2 * t], accO);
        }
        float2 e = up2(accE), o = up2(accO);
        sA[c * 36 + 2 * m] = e.x + e.y;
        sA[c * 36 + 2 * m + 1] = o.x + o.y;
    }
    __syncthreads();

    // IDWT level 1 into ys[nn][c]: pairs nn = 2m, 2m+1 (m = 0..31)
    for (int idx = tid; idx < 64 * 32; idx += 256) {
        int c = idx >> 5, m = idx & 31;
        const float* A = &sA[c * 36 + m];
        const float* D = &sD[c * 36 + m];
        u64 accE = 0ull, accO = 0ull;
#pragma unroll
        for (int t = 0; t < 4; t++) {
            u64 ad = pk2(A[t], D[t]);
            accE = ffma2(ad, lh[2 * t + 1], accE);
            accO = ffma2(ad, lh[2 * t], accO);
        }
        float2 e = up2(accE), o = up2(accO);
        ys[(2 * m) * 65 + c] = e.x + e.y;
        ys[(2 * m + 1) * 65 + c] = o.x + o.y;
    }
    __syncthreads();

    // dense shortcut (f32x2) + add + mish; thread: 2 nn (nn, nn+32) x 8 c
    // x rows offset by +6 in the extended window.
    int nn = tid >> 3;
    int lg = tid & 7;
    int g = lg * 4;
    const ulonglong2* dk2 = reinterpret_cast<const ulonglong2*>(dk);
    u64 bi0 = pk2(bs[g], bs[g + 1]);
    u64 bi1 = pk2(bs[g + 2], bs[g + 3]);
    u64 bi2 = pk2(bs[g + 32], bs[g + 33]);
    u64 bi3 = pk2(bs[g + 34], bs[g + 35]);
    u64 a00 = bi0, a01 = bi1, a02 = bi2, a03 = bi3;
    u64 a10 = bi0, a11 = bi1, a12 = bi2, a13 = bi3;
    const float* xr0 = &xs[(nn + 6) * 65];
    const float* xr1 = &xs[(nn + 38) * 65];
#pragma unroll
    for (int i = 0; i < 64; i++) {
        float xv0 = xr0[i];
        float xv1 = xr1[i];
        u64 p0 = pk2(xv0, xv0), p1 = pk2(xv1, xv1);
        ulonglong2 w0 = __ldg(&dk2[i * 16 + lg]);
        ulonglong2 w1 = __ldg(&dk2[i * 16 + 8 + lg]);
        a00 = ffma2(p0, w0.x, a00); a01 = ffma2(p0, w0.y, a01);
        a02 = ffma2(p0, w1.x, a02); a03 = ffma2(p0, w1.y, a03);
        a10 = ffma2(p1, w0.x, a10); a11 = ffma2(p1, w0.y, a11);
        a12 = ffma2(p1, w1.x, a12); a13 = ffma2(p1, w1.y, a13);
    }
#pragma unroll
    for (int h = 0; h < 2; h++) {
        int row = nn + h * 32;
        float2 q0_ = up2(h ? a10 : a00), q1_ = up2(h ? a11 : a01);
        float2 q2_ = up2(h ? a12 : a02), q3_ = up2(h ? a13 : a03);
        float v0[4] = {q0_.x, q0_.y, q1_.x, q1_.y};
        float v1[4] = {q2_.x, q2_.y, q3_.x, q3_.y};
#pragma unroll
        for (int u = 0; u < 4; u++) {
            v0[u] = mish_f(v0[u] + ys[row * 65 + g + u]);
            v1[u] = mish_f(v1[u] + ys[row * 65 + g + 32 + u]);
        }
        float4* op = reinterpret_cast<float4*>(&out[((size_t)b * N0 + n0 + row) * CB]);
        op[lg] = make_float4(v0[0], v0[1], v0[2], v0[3]);
        op[8 + lg] = make_float4(v1[0], v1[1], v1[2], v1[3]);
    }
}

// ---------------------------------------------------------------------------
extern "C" void kernel_launch(void* const* d_in, const int* in_sizes, int n_in,
                              void* d_out, int out_size) {
    (void)in_sizes; (void)n_in; (void)out_size;
    const float* x    = (const float*)d_in[0];
    const float* w1   = (const float*)d_in[1];
    const float* w2   = (const float*)d_in[2];
    const float* dk   = (const float*)d_in[3];
    const float* bias = (const float*)d_in[4];
    float* out = (float*)d_out;

    float *a2, *d2, *d3, *a4, *d4;
    float *a4t, *d4t, *a4mt, *d4mt, *a4m, *d4m, *wt1, *wt2;
    cudaGetSymbolAddress((void**)&a2,   g_a2);
    cudaGetSymbolAddress((void**)&d2,   g_d2);
    cudaGetSymbolAddress((void**)&d3,   g_d3);
    cudaGetSymbolAddress((void**)&a4,   g_a4);
    cudaGetSymbolAddress((void**)&d4,   g_d4);
    cudaGetSymbolAddress((void**)&a4t,  g_a4t);
    cudaGetSymbolAddress((void**)&d4t,  g_d4t);
    cudaGetSymbolAddress((void**)&a4mt, g_a4mt);
    cudaGetSymbolAddress((void**)&d4mt, g_d4mt);
    cudaGetSymbolAddress((void**)&a4m,  g_a4m);
    cudaGetSymbolAddress((void**)&d4m,  g_d4m);
    cudaGetSymbolAddress((void**)&wt1,  g_wt1);
    cudaGetSymbolAddress((void**)&wt2,  g_wt2);

    const int K1_SMEM = (2 * 32 * 139 + 2 * 32 * 68) * (int)sizeof(float);  // 52992 B
    const int K7_SMEM = (5070 + 4160 + 2304 + 2304 + 1408 + 1408 + 64) * (int)sizeof(float); // 66872 B
    cudaFuncSetAttribute(dwt12_kernel, cudaFuncAttributeMaxDynamicSharedMemorySize, K1_SMEM);
    cudaFuncSetAttribute(ifinal2_kernel, cudaFuncAttributeMaxDynamicSharedMemorySize, K7_SMEM);

    dim3 trb(32, 8);
    // 1. fused transpose + DWT L1 + L2 (d1 no longer materialized)
    dwt12_kernel<<<dim3(33, 64), 256, K1_SMEM>>>(x, a2, d2);
    // 2. fused DWT L3 + L4
    dwt34_kernel<<<R_TOT, 256>>>(a2, d3, a4, d4);
    // 3. forward transposes
    tr4_kernel<<<dim3((M4 + 31) / 32, 4096 / 32, 4), trb>>>(a4, d4, w1, w2, a4t, d4t, wt1, wt2);
    // 4. channel mix
    mix_kernel<<<dim3(M4, 2), 256>>>(a4t, d4t, wt1, wt2, a4mt, d4mt);
    // 5. transpose mixed back
    tr2_kernel<<<dim3(R_TOT / 32, (M4 + 31) / 32, 2), trb>>>(a4mt, d4mt, a4m, d4m);
    // 6. fused IDWT L4->3->2
    idwt432_kernel<<<R_TOT, 256>>>(a4m, d4m, d3, a2);
    // 7. fused IDWT L2->1 + L1->0 (d1 recomputed in-block) + dense + mish
    ifinal2_kernel<<<dim3(N0 / 64, BB), 256, K7_SMEM>>>(a2, d2, x, dk, bias, out);
}